// round 1
// baseline (speedup 1.0000x reference)
#include <cuda_runtime.h>
#include <cstddef>

// ---------------------------------------------------------------------------
// GroupedQueryAttention: B=2, S=2048, D_IN=2048, 32 heads x 64, 8 KV groups
// Outputs (flattened into d_out, metadata order):
//   out    [2,2048,2048]      -> offset 0
//   keys   [2,8,2048,64]      -> offset 8388608
//   values [2,8,2048,64]      -> offset 10485760
// ---------------------------------------------------------------------------

namespace {
constexpr int kB    = 2;
constexpr int kS    = 2048;
constexpr int kDin  = 2048;
constexpr int kDout = 2048;
constexpr int kNH   = 32;
constexpr int kNKV  = 8;
constexpr int kHD   = 64;
constexpr int kGS   = 4;                 // heads per KV group
constexpr int kM    = kB * kS;           // 4096 rows
constexpr int kDkv  = kNKV * kHD;        // 512
}

// Scratch (device globals: no allocation allowed)
__device__ float g_Q[(size_t)kM * kDout];     // 33.5 MB
__device__ float g_ctx[(size_t)kM * kDout];   // 33.5 MB

// ---------------------------------------------------------------------------
// NT GEMM: C[m,n] = sum_k A[m,k] * B[n,k]   (A:[M,K] row-major, B:[N,K] row-major)
// MODE 0: plain row-major C[M,N]
// MODE 1: KV-cache epilogue: m=(b,s), n=(g,d) -> C[((b*8+g)*2048+s)*64+d]
// Tiles: BM=128, BN=64, BK=16; 256 threads; 8x4 register tile per thread.
// ---------------------------------------------------------------------------
template <int MODE>
__global__ __launch_bounds__(256)
void gemm_nt_kernel(const float* __restrict__ A, const float* __restrict__ Bm,
                    float* __restrict__ C, int M, int N, int K)
{
    constexpr int BM = 128, BN = 64, BK = 16;
    __shared__ float As[BK][BM];
    __shared__ float Bs[BK][BN];

    const int t  = threadIdx.x;
    const int tx = t & 15;        // 0..15 -> 4 cols each
    const int ty = t >> 4;        // 0..15 -> 8 rows each
    const int rowBase = blockIdx.y * BM;
    const int colBase = blockIdx.x * BN;
    const int ar = t >> 2;        // 0..63
    const int ac = t & 3;         // k-quad 0..3

    float acc[8][4];
#pragma unroll
    for (int i = 0; i < 8; i++)
#pragma unroll
        for (int j = 0; j < 4; j++) acc[i][j] = 0.f;

    for (int k0 = 0; k0 < K; k0 += BK) {
        const float4 a0 = *(const float4*)&A[(size_t)(rowBase + ar)      * K + k0 + ac * 4];
        const float4 a1 = *(const float4*)&A[(size_t)(rowBase + ar + 64) * K + k0 + ac * 4];
        const float4 b0 = *(const float4*)&Bm[(size_t)(colBase + ar)     * K + k0 + ac * 4];
        __syncthreads();
        As[ac * 4 + 0][ar]      = a0.x;
        As[ac * 4 + 1][ar]      = a0.y;
        As[ac * 4 + 2][ar]      = a0.z;
        As[ac * 4 + 3][ar]      = a0.w;
        As[ac * 4 + 0][ar + 64] = a1.x;
        As[ac * 4 + 1][ar + 64] = a1.y;
        As[ac * 4 + 2][ar + 64] = a1.z;
        As[ac * 4 + 3][ar + 64] = a1.w;
        Bs[ac * 4 + 0][ar] = b0.x;
        Bs[ac * 4 + 1][ar] = b0.y;
        Bs[ac * 4 + 2][ar] = b0.z;
        Bs[ac * 4 + 3][ar] = b0.w;
        __syncthreads();

#pragma unroll
        for (int k = 0; k < BK; k++) {
            const float4 av0 = *(const float4*)&As[k][ty * 8];
            const float4 av1 = *(const float4*)&As[k][ty * 8 + 4];
            const float4 bv  = *(const float4*)&Bs[k][tx * 4];
            const float a[8] = {av0.x, av0.y, av0.z, av0.w, av1.x, av1.y, av1.z, av1.w};
            const float b[4] = {bv.x, bv.y, bv.z, bv.w};
#pragma unroll
            for (int i = 0; i < 8; i++)
#pragma unroll
                for (int j = 0; j < 4; j++) acc[i][j] += a[i] * b[j];
        }
    }

#pragma unroll
    for (int i = 0; i < 8; i++) {
        const int m = rowBase + ty * 8 + i;
        if (MODE == 0) {
            float4 o = make_float4(acc[i][0], acc[i][1], acc[i][2], acc[i][3]);
            *(float4*)&C[(size_t)m * N + colBase + tx * 4] = o;
        } else {
            const int bb = m >> 11;       // m / kS
            const int ss = m & (kS - 1);
#pragma unroll
            for (int j = 0; j < 4; j++) {
                const int n = colBase + tx * 4 + j;
                const int g = n >> 6;
                const int d = n & 63;
                C[((((size_t)bb * kNKV + g) * kS + ss) << 6) + d] = acc[i][j];
            }
        }
    }
}

// ---------------------------------------------------------------------------
// Causal flash attention, fp32. One query row per thread; 128 rows per block.
// grid = (S/128, B*NH). K/V read from the [b,g,s,d] cache layout in d_out.
// ---------------------------------------------------------------------------
__global__ __launch_bounds__(128)
void attn_kernel(const float* __restrict__ Q, const float* __restrict__ Kc,
                 const float* __restrict__ Vc, float* __restrict__ ctx)
{
    __shared__ float Ks[64][64];
    __shared__ float Vs[64][64];

    const int t  = threadIdx.x;
    const int bh = blockIdx.y;
    const int b  = bh / kNH;
    const int h  = bh % kNH;
    const int g  = h / kGS;
    const int q_idx = blockIdx.x * 128 + t;

    // Load this thread's query row (64 floats) into registers
    const float* qp = &Q[((size_t)(b * kS + q_idx)) * kDout + h * kHD];
    float q[64];
#pragma unroll
    for (int c = 0; c < 16; c++) {
        const float4 v4 = *(const float4*)&qp[c * 4];
        q[4 * c + 0] = v4.x; q[4 * c + 1] = v4.y;
        q[4 * c + 2] = v4.z; q[4 * c + 3] = v4.w;
    }

    float m = -1e30f, l = 0.f;
    float acc[64];
#pragma unroll
    for (int d = 0; d < 64; d++) acc[d] = 0.f;

    const float* kbase = &Kc[((size_t)(b * kNKV + g)) * kS * kHD];
    const float* vbase = &Vc[((size_t)(b * kNKV + g)) * kS * kHD];

    const int ntiles = blockIdx.x * 2 + 2;   // 64-key tiles touching this row block
    for (int kt = 0; kt < ntiles; kt++) {
        __syncthreads();
        // Cooperative load of K and V tiles (64x64 fp32 each)
#pragma unroll
        for (int i = 0; i < 8; i++) {
            const int idx = t + i * 128;         // 0..1023 float4 slots
            const int r   = idx >> 4;
            const int c4  = (idx & 15) * 4;
            *(float4*)&Ks[r][c4] = *(const float4*)&kbase[(size_t)(kt * 64 + r) * kHD + c4];
            *(float4*)&Vs[r][c4] = *(const float4*)&vbase[(size_t)(kt * 64 + r) * kHD + c4];
        }
        __syncthreads();

        const int jend = min(64, q_idx - kt * 64 + 1);  // causal bound
        for (int j = 0; j < jend; j++) {
            float s = 0.f;
#pragma unroll
            for (int c = 0; c < 16; c++) {
                const float4 kv = *(const float4*)&Ks[j][4 * c];
                s += q[4 * c + 0] * kv.x + q[4 * c + 1] * kv.y
                   + q[4 * c + 2] * kv.z + q[4 * c + 3] * kv.w;
            }
            s *= 0.125f;   // 1/sqrt(64)
            const float mn   = fmaxf(m, s);
            const float corr = __expf(m - mn);
            const float p    = __expf(s - mn);
            m = mn;
            l = l * corr + p;
#pragma unroll
            for (int c = 0; c < 16; c++) {
                const float4 vv = *(const float4*)&Vs[j][4 * c];
                acc[4 * c + 0] = acc[4 * c + 0] * corr + p * vv.x;
                acc[4 * c + 1] = acc[4 * c + 1] * corr + p * vv.y;
                acc[4 * c + 2] = acc[4 * c + 2] * corr + p * vv.z;
                acc[4 * c + 3] = acc[4 * c + 3] * corr + p * vv.w;
            }
        }
    }

    const float inv = 1.f / l;
    float* op = &ctx[((size_t)(b * kS + q_idx)) * kDout + h * kHD];
#pragma unroll
    for (int c = 0; c < 16; c++) {
        float4 o = make_float4(acc[4 * c + 0] * inv, acc[4 * c + 1] * inv,
                               acc[4 * c + 2] * inv, acc[4 * c + 3] * inv);
        *(float4*)&op[4 * c] = o;
    }
}

// ---------------------------------------------------------------------------
extern "C" void kernel_launch(void* const* d_in, const int* in_sizes, int n_in,
                              void* d_out, int out_size)
{
    const float* x  = (const float*)d_in[0];
    const float* Wq = (const float*)d_in[1];
    const float* Wk = (const float*)d_in[2];
    const float* Wv = (const float*)d_in[3];
    const float* Wo = (const float*)d_in[4];

    float* out    = (float*)d_out;
    float* keys   = out + (size_t)kM * kDout;                 // 8388608
    float* values = keys + (size_t)kB * kNKV * kS * kHD;      // +2097152

    float* Qp;  cudaGetSymbolAddress((void**)&Qp,  g_Q);
    float* Cxp; cudaGetSymbolAddress((void**)&Cxp, g_ctx);

    // Projections
    gemm_nt_kernel<0><<<dim3(kDout / 64, kM / 128), 256>>>(x, Wq, Qp,     kM, kDout, kDin);
    gemm_nt_kernel<1><<<dim3(kDkv  / 64, kM / 128), 256>>>(x, Wk, keys,   kM, kDkv,  kDin);
    gemm_nt_kernel<1><<<dim3(kDkv  / 64, kM / 128), 256>>>(x, Wv, values, kM, kDkv,  kDin);

    // Causal GQA attention -> ctx
    attn_kernel<<<dim3(kS / 128, kB * kNH), 128>>>(Qp, keys, values, Cxp);

    // Output projection
    gemm_nt_kernel<0><<<dim3(kDout / 64, kM / 128), 256>>>(Cxp, Wo, out, kM, kDout, kDin);
}

// round 3
// speedup vs baseline: 2.6768x; 2.6768x over previous
#include <cuda_runtime.h>
#include <cstdint>
#include <cstddef>

// ---------------------------------------------------------------------------
// GroupedQueryAttention: B=2, S=2048, D_IN=2048, 32 heads x 64, 8 KV groups
// d_out layout: out [2,2048,2048] | keys [2,8,2048,64] | values [2,8,2048,64]
// All heavy math via tf32 mma.sync (legacy tensor-core path valid on
// compute_103 virtual arch — tcgen05 is NOT available under this toolchain).
// ---------------------------------------------------------------------------

namespace {
constexpr int kB    = 2;
constexpr int kS    = 2048;
constexpr int kDin  = 2048;
constexpr int kDout = 2048;
constexpr int kNH   = 32;
constexpr int kNKV  = 8;
constexpr int kHD   = 64;
constexpr int kM    = kB * kS;       // 4096
constexpr int kDkv  = kNKV * kHD;    // 512
}

// Scratch (device globals: no allocation allowed)
__device__ float g_Q  [(size_t)kM * kDout];
__device__ float g_ctx[(size_t)kM * kDout];

// ------------------------- helpers -----------------------------------------
__device__ __forceinline__ uint32_t smem_u32(const void* p) {
    uint32_t a;
    asm("{ .reg .u64 t; cvta.to.shared.u64 t, %1; cvt.u32.u64 %0, t; }" : "=r"(a) : "l"(p));
    return a;
}
__device__ __forceinline__ uint32_t f2tf(float f) {
    uint32_t r;
    asm("cvt.rna.tf32.f32 %0, %1;" : "=r"(r) : "f"(f));
    return r;
}
__device__ __forceinline__ void mma_tf32(float& c0, float& c1, float& c2, float& c3,
                                         uint32_t a0, uint32_t a1, uint32_t a2, uint32_t a3,
                                         uint32_t b0, uint32_t b1) {
    asm volatile(
        "mma.sync.aligned.m16n8k8.row.col.f32.tf32.tf32.f32 "
        "{%0,%1,%2,%3}, {%4,%5,%6,%7}, {%8,%9}, {%0,%1,%2,%3};"
        : "+f"(c0), "+f"(c1), "+f"(c2), "+f"(c3)
        : "r"(a0), "r"(a1), "r"(a2), "r"(a3), "r"(b0), "r"(b1));
}
__device__ __forceinline__ void cp_async16(uint32_t dst, const void* src) {
    asm volatile("cp.async.cg.shared.global [%0], [%1], 16;" :: "r"(dst), "l"(src));
}
#define CP_COMMIT() asm volatile("cp.async.commit_group;" ::: "memory")
#define CP_WAIT(n)  asm volatile("cp.async.wait_group %0;" :: "n"(n) : "memory")

// ---------------------------------------------------------------------------
// tf32 GEMM: C[m,n] = sum_k A[m,k] * B[n,k]  (both row-major, K contiguous)
// BM=128, BN=128, BK=32, 256 threads (8 warps, 4x2 warp grid, 32x64 per warp).
// smem stride 36 (== 4 mod 32) makes all fragment LDS conflict-free.
// MODE 0: row-major C[M,N].  MODE 1: KV-cache layout [b,g,s,d].
// ---------------------------------------------------------------------------
namespace {
constexpr int BM = 128, BN = 128, BK = 32, STR = 36;
constexpr int kGemmSmem = 2 * (BM * STR + BN * STR) * 4;   // 73728 bytes
}

template <int MODE>
__global__ __launch_bounds__(256)
void gemm_tf32(const float* __restrict__ A, const float* __restrict__ Bw,
               float* __restrict__ C, int M, int N, int K)
{
    extern __shared__ float sm[];
    float* AsBuf[2] = { sm,            sm + (BM + BN) * STR };
    float* BsBuf[2] = { sm + BM * STR, sm + (BM + BN) * STR + BM * STR };

    const int t    = threadIdx.x;
    const int lane = t & 31;
    const int wid  = t >> 5;
    const int wm   = (wid & 3) * 32;
    const int wn   = (wid >> 2) * 64;
    const int rowBase = blockIdx.y * BM;
    const int colBase = blockIdx.x * BN;

    float acc[2][8][4] = {};

    auto load_tile = [&](int kt, int buf) {
        const float* Ag = A  + (size_t)rowBase * K + kt * BK;
        const float* Bg = Bw + (size_t)colBase * K + kt * BK;
        const uint32_t sa = smem_u32(AsBuf[buf]);
        const uint32_t sb = smem_u32(BsBuf[buf]);
#pragma unroll
        for (int i = 0; i < 4; i++) {
            const int v = t + i * 256;            // 0..1023
            const int r = v >> 3, c4 = (v & 7) * 4;
            cp_async16(sa + (r * STR + c4) * 4, Ag + (size_t)r * K + c4);
        }
#pragma unroll
        for (int i = 0; i < 4; i++) {
            const int v = t + i * 256;
            const int r = v >> 3, c4 = (v & 7) * 4;
            cp_async16(sb + (r * STR + c4) * 4, Bg + (size_t)r * K + c4);
        }
        CP_COMMIT();
    };

    const int NC = K / BK;
    load_tile(0, 0);

    for (int c = 0; c < NC; c++) {
        const int buf = c & 1;
        if (c + 1 < NC) { load_tile(c + 1, buf ^ 1); CP_WAIT(1); }
        else            { CP_WAIT(0); }
        __syncthreads();

        const float* as = AsBuf[buf];
        const float* bs = BsBuf[buf];
#pragma unroll
        for (int ks = 0; ks < 4; ks++) {
            uint32_t af[2][4];
#pragma unroll
            for (int mt = 0; mt < 2; mt++) {
                const float* p = as + (wm + mt * 16 + (lane >> 2)) * STR + ks * 8 + (lane & 3);
                af[mt][0] = f2tf(p[0]);
                af[mt][1] = f2tf(p[8 * STR]);
                af[mt][2] = f2tf(p[4]);
                af[mt][3] = f2tf(p[8 * STR + 4]);
            }
#pragma unroll
            for (int nt = 0; nt < 8; nt++) {
                const float* p = bs + (wn + nt * 8 + (lane >> 2)) * STR + ks * 8 + (lane & 3);
                const uint32_t b0 = f2tf(p[0]);
                const uint32_t b1 = f2tf(p[4]);
                mma_tf32(acc[0][nt][0], acc[0][nt][1], acc[0][nt][2], acc[0][nt][3],
                         af[0][0], af[0][1], af[0][2], af[0][3], b0, b1);
                mma_tf32(acc[1][nt][0], acc[1][nt][1], acc[1][nt][2], acc[1][nt][3],
                         af[1][0], af[1][1], af[1][2], af[1][3], b0, b1);
            }
        }
        __syncthreads();
    }

    // epilogue
#pragma unroll
    for (int mt = 0; mt < 2; mt++)
#pragma unroll
    for (int nt = 0; nt < 8; nt++) {
        const int row0 = rowBase + wm + mt * 16 + (lane >> 2);
        const int col  = colBase + wn + nt * 8 + 2 * (lane & 3);
        if (MODE == 0) {
            *(float2*)&C[(size_t)row0 * N + col] =
                make_float2(acc[mt][nt][0], acc[mt][nt][1]);
            *(float2*)&C[(size_t)(row0 + 8) * N + col] =
                make_float2(acc[mt][nt][2], acc[mt][nt][3]);
        } else {
            const int g = col >> 6, d = col & 63;
            {
                const int bb = row0 >> 11, ss = row0 & (kS - 1);
                *(float2*)&C[((((size_t)bb * kNKV + g) * kS + ss) << 6) + d] =
                    make_float2(acc[mt][nt][0], acc[mt][nt][1]);
            }
            {
                const int r1 = row0 + 8;
                const int bb = r1 >> 11, ss = r1 & (kS - 1);
                *(float2*)&C[((((size_t)bb * kNKV + g) * kS + ss) << 6) + d] =
                    make_float2(acc[mt][nt][2], acc[mt][nt][3]);
            }
        }
    }
}

// ---------------------------------------------------------------------------
// Causal GQA flash attention via tf32 mma.
// Block: 256 threads (8 warps x 16 q-rows = 128 rows). grid = (S/128, B*NH).
// Per 64-key tile: S = Q*K^T (mma), online softmax on C-fragments,
// P -> per-warp smem (tf32 bits) -> A-fragments, O += P*V (mma).
// smem: Ks[d][key] str 72 | Vs[key][d] str 72 | Sp per-warp 16x68.
// ---------------------------------------------------------------------------
namespace {
constexpr int kAttSmem = (2 * 64 * 72 + 8 * 16 * 68) * 4;   // 71680 bytes
}

__global__ __launch_bounds__(256)
void attn_mma(const float* __restrict__ Q, const float* __restrict__ Kc,
              const float* __restrict__ Vc, float* __restrict__ ctx)
{
    extern __shared__ float sm[];
    float* Ks = sm;                 // [64 d][72] -> [d][key]
    float* Vs = sm + 64 * 72;       // [64 key][72] -> [key][d]
    float* Sp = sm + 2 * 64 * 72;   // 8 warps x 16 x 68

    const int t    = threadIdx.x;
    const int lane = t & 31;
    const int wid  = t >> 5;
    const int bh = blockIdx.y;
    const int b  = bh >> 5;
    const int h  = bh & 31;
    const int g  = h >> 2;
    const int qb = blockIdx.x * 128;
    const int wm = wid * 16;

    // ---- stage Q tile into smem (reuse Ks/Vs region), then to A-fragments
    float* Qs = sm;                 // 128 x 68 = 34816 B < 36864 B (Ks+Vs)
    const float* qg = Q + ((size_t)(b * kS + qb)) * kDout + h * kHD;
#pragma unroll
    for (int i = 0; i < 8; i++) {
        const int v = t + i * 256;              // 0..2047 float4 slots
        const int r = v >> 4, c4 = (v & 15) * 4;
        *(float4*)&Qs[r * 68 + c4] = *(const float4*)&qg[(size_t)r * kDout + c4];
    }
    __syncthreads();
    uint32_t qf[8][4];
    {
        const float* p = Qs + (wm + (lane >> 2)) * 68 + (lane & 3);
#pragma unroll
        for (int ks = 0; ks < 8; ks++) {
            qf[ks][0] = f2tf(0.125f * p[ks * 8]);
            qf[ks][1] = f2tf(0.125f * p[8 * 68 + ks * 8]);
            qf[ks][2] = f2tf(0.125f * p[ks * 8 + 4]);
            qf[ks][3] = f2tf(0.125f * p[8 * 68 + ks * 8 + 4]);
        }
    }
    __syncthreads();

    float oacc[8][4] = {};
    float m0 = -1e30f, m1 = -1e30f, l0 = 0.f, l1 = 0.f;

    const float* kg = Kc + ((size_t)(b * kNKV + g)) * kS * kHD;
    const float* vg = Vc + ((size_t)(b * kNKV + g)) * kS * kHD;
    uint32_t* spi = (uint32_t*)(Sp + wid * 16 * 68);

    const int ntk = blockIdx.x * 2 + 2;
    for (int kt = 0; kt < ntk; kt++) {
        // K transposed store: lanes vary along `key` -> conflict-free STS
#pragma unroll
        for (int i = 0; i < 4; i++) {
            const int v = t + i * 256;          // 0..1023
            const int key = v & 63, dg = v >> 6;
            const float4 kk = *(const float4*)&kg[(size_t)(kt * 64 + key) * kHD + dg * 4];
            Ks[(dg * 4 + 0) * 72 + key] = kk.x;
            Ks[(dg * 4 + 1) * 72 + key] = kk.y;
            Ks[(dg * 4 + 2) * 72 + key] = kk.z;
            Ks[(dg * 4 + 3) * 72 + key] = kk.w;
        }
        // V natural store
#pragma unroll
        for (int i = 0; i < 4; i++) {
            const int v = t + i * 256;
            const int key = v >> 4, c4 = (v & 15) * 4;
            *(float4*)&Vs[key * 72 + c4] =
                *(const float4*)&vg[(size_t)(kt * 64 + key) * kHD + c4];
        }
        __syncthreads();

        // ---- S = Q K^T
        float sacc[8][4] = {};
#pragma unroll
        for (int ks = 0; ks < 8; ks++) {
            const float* p = Ks + (ks * 8 + (lane & 3)) * 72 + (lane >> 2);
#pragma unroll
            for (int nt = 0; nt < 8; nt++) {
                const uint32_t b0 = f2tf(p[nt * 8]);
                const uint32_t b1 = f2tf(p[4 * 72 + nt * 8]);
                mma_tf32(sacc[nt][0], sacc[nt][1], sacc[nt][2], sacc[nt][3],
                         qf[ks][0], qf[ks][1], qf[ks][2], qf[ks][3], b0, b1);
            }
        }

        // ---- causal mask (only tiles that can cross the diagonal)
        const int r0 = qb + wm + (lane >> 2);
        const int r1 = r0 + 8;
        if (kt * 64 + 63 > qb + wm) {
#pragma unroll
            for (int nt = 0; nt < 8; nt++) {
                const int c0 = kt * 64 + nt * 8 + 2 * (lane & 3);
                if (c0     > r0) sacc[nt][0] = -1e30f;
                if (c0 + 1 > r0) sacc[nt][1] = -1e30f;
                if (c0     > r1) sacc[nt][2] = -1e30f;
                if (c0 + 1 > r1) sacc[nt][3] = -1e30f;
            }
        }

        // ---- online softmax
        float t0 = -1e30f, t1 = -1e30f;
#pragma unroll
        for (int nt = 0; nt < 8; nt++) {
            t0 = fmaxf(t0, fmaxf(sacc[nt][0], sacc[nt][1]));
            t1 = fmaxf(t1, fmaxf(sacc[nt][2], sacc[nt][3]));
        }
        t0 = fmaxf(t0, __shfl_xor_sync(0xFFFFFFFFu, t0, 1));
        t0 = fmaxf(t0, __shfl_xor_sync(0xFFFFFFFFu, t0, 2));
        t1 = fmaxf(t1, __shfl_xor_sync(0xFFFFFFFFu, t1, 1));
        t1 = fmaxf(t1, __shfl_xor_sync(0xFFFFFFFFu, t1, 2));
        const float mn0 = fmaxf(m0, t0);
        const float mn1 = fmaxf(m1, t1);
        const float corr0 = __expf(m0 - mn0);
        const float corr1 = __expf(m1 - mn1);
        m0 = mn0; m1 = mn1;

        float rs0 = 0.f, rs1 = 0.f;
#pragma unroll
        for (int nt = 0; nt < 8; nt++) {
            sacc[nt][0] = __expf(sacc[nt][0] - mn0);
            sacc[nt][1] = __expf(sacc[nt][1] - mn0);
            sacc[nt][2] = __expf(sacc[nt][2] - mn1);
            sacc[nt][3] = __expf(sacc[nt][3] - mn1);
            rs0 += sacc[nt][0] + sacc[nt][1];
            rs1 += sacc[nt][2] + sacc[nt][3];
        }
        rs0 += __shfl_xor_sync(0xFFFFFFFFu, rs0, 1);
        rs0 += __shfl_xor_sync(0xFFFFFFFFu, rs0, 2);
        rs1 += __shfl_xor_sync(0xFFFFFFFFu, rs1, 1);
        rs1 += __shfl_xor_sync(0xFFFFFFFFu, rs1, 2);
        l0 = l0 * corr0 + rs0;
        l1 = l1 * corr1 + rs1;

#pragma unroll
        for (int nt = 0; nt < 8; nt++) {
            oacc[nt][0] *= corr0; oacc[nt][1] *= corr0;
            oacc[nt][2] *= corr1; oacc[nt][3] *= corr1;
        }

        // ---- P (tf32 bits) -> per-warp smem, re-enter as A-fragments
        {
            const int rr = lane >> 2;
            const int cc = 2 * (lane & 3);
#pragma unroll
            for (int nt = 0; nt < 8; nt++) {
                spi[rr * 68 + nt * 8 + cc]           = f2tf(sacc[nt][0]);
                spi[rr * 68 + nt * 8 + cc + 1]       = f2tf(sacc[nt][1]);
                spi[(rr + 8) * 68 + nt * 8 + cc]     = f2tf(sacc[nt][2]);
                spi[(rr + 8) * 68 + nt * 8 + cc + 1] = f2tf(sacc[nt][3]);
            }
        }
        __syncwarp();

        // ---- O += P V
#pragma unroll
        for (int ks = 0; ks < 8; ks++) {
            const uint32_t* pp = spi + (lane >> 2) * 68 + ks * 8 + (lane & 3);
            const uint32_t a0 = pp[0];
            const uint32_t a1 = pp[8 * 68];
            const uint32_t a2 = pp[4];
            const uint32_t a3 = pp[8 * 68 + 4];
            const float* pv = Vs + (ks * 8 + (lane & 3)) * 72 + (lane >> 2);
#pragma unroll
            for (int nt = 0; nt < 8; nt++) {
                const uint32_t b0 = f2tf(pv[nt * 8]);
                const uint32_t b1 = f2tf(pv[4 * 72 + nt * 8]);
                mma_tf32(oacc[nt][0], oacc[nt][1], oacc[nt][2], oacc[nt][3],
                         a0, a1, a2, a3, b0, b1);
            }
        }
        __syncthreads();   // before next tile overwrites Ks/Vs
    }

    // ---- epilogue
    const float inv0 = 1.f / l0;
    const float inv1 = 1.f / l1;
    float* og = ctx + ((size_t)(b * kS + qb + wm + (lane >> 2))) * kDout + h * kHD;
    const int cbase = 2 * (lane & 3);
#pragma unroll
    for (int nt = 0; nt < 8; nt++) {
        const int col = nt * 8 + cbase;
        *(float2*)&og[col] = make_float2(oacc[nt][0] * inv0, oacc[nt][1] * inv0);
        *(float2*)&og[(size_t)8 * kDout + col] =
            make_float2(oacc[nt][2] * inv1, oacc[nt][3] * inv1);
    }
}

// ---------------------------------------------------------------------------
extern "C" void kernel_launch(void* const* d_in, const int* in_sizes, int n_in,
                              void* d_out, int out_size)
{
    const float* x  = (const float*)d_in[0];
    const float* Wq = (const float*)d_in[1];
    const float* Wk = (const float*)d_in[2];
    const float* Wv = (const float*)d_in[3];
    const float* Wo = (const float*)d_in[4];

    float* out    = (float*)d_out;
    float* keys   = out + (size_t)kM * kDout;
    float* values = keys + (size_t)kB * kNKV * kS * kHD;

    float *Qp, *Cxp;
    cudaGetSymbolAddress((void**)&Qp,  g_Q);
    cudaGetSymbolAddress((void**)&Cxp, g_ctx);

    static bool attr_done = false;
    if (!attr_done) {
        cudaFuncSetAttribute(gemm_tf32<0>, cudaFuncAttributeMaxDynamicSharedMemorySize, kGemmSmem);
        cudaFuncSetAttribute(gemm_tf32<1>, cudaFuncAttributeMaxDynamicSharedMemorySize, kGemmSmem);
        cudaFuncSetAttribute(attn_mma,     cudaFuncAttributeMaxDynamicSharedMemorySize, kAttSmem);
        attr_done = true;
    }

    // Projections
    gemm_tf32<0><<<dim3(kDout / BN, kM / BM), 256, kGemmSmem>>>(x, Wq, Qp,     kM, kDout, kDin);
    gemm_tf32<1><<<dim3(kDkv  / BN, kM / BM), 256, kGemmSmem>>>(x, Wk, keys,   kM, kDkv,  kDin);
    gemm_tf32<1><<<dim3(kDkv  / BN, kM / BM), 256, kGemmSmem>>>(x, Wv, values, kM, kDkv,  kDin);

    // Causal GQA attention
    attn_mma<<<dim3(kS / 128, kB * kNH), 256, kAttSmem>>>(Qp, keys, values, Cxp);

    // Output projection
    gemm_tf32<0><<<dim3(kDout / BN, kM / BM), 256, kGemmSmem>>>(Cxp, Wo, out, kM, kDout, kDin);
}

// round 4
// speedup vs baseline: 4.1739x; 1.5593x over previous
#include <cuda_runtime.h>
#include <cstdint>
#include <cstddef>

// ---------------------------------------------------------------------------
// GroupedQueryAttention: B=2, S=2048, D_IN=2048, 32 heads x 64, 8 KV groups
// d_out: out [2,2048,2048] | keys [2,8,2048,64] | values [2,8,2048,64]
// tf32 mma.sync everywhere; operands pre-converted to tf32 bits exactly once;
// all fragments via ldmatrix; P remap via shuffles (no smem round-trip).
// ---------------------------------------------------------------------------

namespace {
constexpr int kB    = 2;
constexpr int kS    = 2048;
constexpr int kDin  = 2048;
constexpr int kDout = 2048;
constexpr int kNH   = 32;
constexpr int kNKV  = 8;
constexpr int kHD   = 64;
constexpr int kM    = kB * kS;       // 4096
constexpr int kDkv  = kNKV * kHD;    // 512
}

// Scratch (device globals: no allocation allowed)
__device__ float    g_Q  [(size_t)kM * kDout];     // tf32 bits, pre-scaled 1/8
__device__ float    g_ctx[(size_t)kM * kDout];     // tf32 bits
__device__ uint32_t g_xT [(size_t)kM    * kDin];
__device__ uint32_t g_wqT[(size_t)kDout * kDin];
__device__ uint32_t g_wkT[(size_t)kDkv  * kDin];
__device__ uint32_t g_wvT[(size_t)kDkv  * kDin];
__device__ uint32_t g_woT[(size_t)kDin  * kDout];

// ------------------------- helpers -----------------------------------------
__device__ __forceinline__ uint32_t smem_u32(const void* p) {
    uint32_t a;
    asm("{ .reg .u64 t; cvta.to.shared.u64 t, %1; cvt.u32.u64 %0, t; }" : "=r"(a) : "l"(p));
    return a;
}
__device__ __forceinline__ uint32_t f2tf(float f) {
    uint32_t r;
    asm("cvt.rna.tf32.f32 %0, %1;" : "=r"(r) : "f"(f));
    return r;
}
__device__ __forceinline__ void mma_tf32(float& c0, float& c1, float& c2, float& c3,
                                         uint32_t a0, uint32_t a1, uint32_t a2, uint32_t a3,
                                         uint32_t b0, uint32_t b1) {
    asm volatile(
        "mma.sync.aligned.m16n8k8.row.col.f32.tf32.tf32.f32 "
        "{%0,%1,%2,%3}, {%4,%5,%6,%7}, {%8,%9}, {%0,%1,%2,%3};"
        : "+f"(c0), "+f"(c1), "+f"(c2), "+f"(c3)
        : "r"(a0), "r"(a1), "r"(a2), "r"(a3), "r"(b0), "r"(b1));
}
#define LDMX4(r, addr)                                                        \
    asm volatile("ldmatrix.sync.aligned.m8n8.x4.shared.b16 {%0,%1,%2,%3}, [%4];" \
        : "=r"((r)[0]), "=r"((r)[1]), "=r"((r)[2]), "=r"((r)[3]) : "r"(addr))
__device__ __forceinline__ void cp_async16(uint32_t dst, const void* src) {
    asm volatile("cp.async.cg.shared.global [%0], [%1], 16;" :: "r"(dst), "l"(src));
}
#define CP_COMMIT() asm volatile("cp.async.commit_group;" ::: "memory")
#define CP_WAIT(n)  asm volatile("cp.async.wait_group %0;" :: "n"(n) : "memory")

// ---------------------------------------------------------------------------
// fp32 -> tf32-bit conversion pass (vectorized)
// ---------------------------------------------------------------------------
__global__ __launch_bounds__(256)
void cvt_tf32(const float4* __restrict__ in, uint4* __restrict__ out, int n4)
{
    int i = blockIdx.x * blockDim.x + threadIdx.x;
    const int stride = gridDim.x * blockDim.x;
    for (; i < n4; i += stride) {
        const float4 v = in[i];
        uint4 o;
        o.x = f2tf(v.x); o.y = f2tf(v.y); o.z = f2tf(v.z); o.w = f2tf(v.w);
        out[i] = o;
    }
}

// ---------------------------------------------------------------------------
// tf32 GEMM on pre-converted operands: C[m,n] = sum_k A[m,k]*B[n,k]
// BM=128, BN=128, BK=32, 256 threads, warp tile 32x64, all frags via ldmatrix.
// MODE 0: fp32 C.  MODE 1: KV-cache fp32.  MODE 2: tf32 bits of 0.125*acc.
// ---------------------------------------------------------------------------
namespace {
constexpr int BM = 128, BN = 128, BK = 32, STR = 36;
constexpr int kBufU32   = (BM + BN) * STR;           // one double-buffer stage
constexpr int kGemmSmem = 2 * kBufU32 * 4;           // 73728 bytes
}

template <int MODE>
__global__ __launch_bounds__(256)
void gemm_tf32(const uint32_t* __restrict__ A, const uint32_t* __restrict__ Bw,
               float* __restrict__ C, int M, int N, int K)
{
    extern __shared__ uint32_t smu[];
    const uint32_t smBase = smem_u32(smu);

    const int t    = threadIdx.x;
    const int lane = t & 31;
    const int wid  = t >> 5;
    const int wm   = (wid & 3) * 32;
    const int wn   = (wid >> 2) * 64;
    const int rowBase = blockIdx.y * BM;
    const int colBase = blockIdx.x * BN;

    float acc[2][8][4] = {};

    auto load_tile = [&](int kt, int buf) {
        const uint32_t* Ag = A  + (size_t)rowBase * K + kt * BK;
        const uint32_t* Bg = Bw + (size_t)colBase * K + kt * BK;
        const uint32_t dst = smBase + buf * kBufU32 * 4;
#pragma unroll
        for (int i = 0; i < 4; i++) {
            const int v = t + i * 256;
            const int r = v >> 3, c4 = (v & 7) * 4;
            cp_async16(dst + (r * STR + c4) * 4, Ag + (size_t)r * K + c4);
        }
#pragma unroll
        for (int i = 0; i < 4; i++) {
            const int v = t + i * 256;
            const int r = v >> 3, c4 = (v & 7) * 4;
            cp_async16(dst + (BM * STR + r * STR + c4) * 4, Bg + (size_t)r * K + c4);
        }
        CP_COMMIT();
    };

    // per-lane ldmatrix byte offsets
    const uint32_t aOff = ((wm + (lane & 7) + ((lane >> 3) & 1) * 8) * STR + (lane >> 4) * 4) * 4;
    const uint32_t bOff = ((wn + ((lane >> 4) & 1) * 8 + (lane & 7)) * STR + ((lane >> 3) & 1) * 4) * 4;

    const int NC = K / BK;
    load_tile(0, 0);

    for (int c = 0; c < NC; c++) {
        const int buf = c & 1;
        if (c + 1 < NC) { load_tile(c + 1, buf ^ 1); CP_WAIT(1); }
        else            { CP_WAIT(0); }
        __syncthreads();

        const uint32_t ba = smBase + buf * kBufU32 * 4;
        const uint32_t bb = ba + BM * STR * 4;
#pragma unroll
        for (int ks = 0; ks < 4; ks++) {
            uint32_t af[2][4];
            LDMX4(af[0], ba + aOff + (ks * 8) * 4);
            LDMX4(af[1], ba + aOff + (16 * STR + ks * 8) * 4);
#pragma unroll
            for (int p = 0; p < 4; p++) {
                uint32_t bf[4];
                LDMX4(bf, bb + bOff + (p * 16 * STR + ks * 8) * 4);
                mma_tf32(acc[0][2*p][0], acc[0][2*p][1], acc[0][2*p][2], acc[0][2*p][3],
                         af[0][0], af[0][1], af[0][2], af[0][3], bf[0], bf[1]);
                mma_tf32(acc[1][2*p][0], acc[1][2*p][1], acc[1][2*p][2], acc[1][2*p][3],
                         af[1][0], af[1][1], af[1][2], af[1][3], bf[0], bf[1]);
                mma_tf32(acc[0][2*p+1][0], acc[0][2*p+1][1], acc[0][2*p+1][2], acc[0][2*p+1][3],
                         af[0][0], af[0][1], af[0][2], af[0][3], bf[2], bf[3]);
                mma_tf32(acc[1][2*p+1][0], acc[1][2*p+1][1], acc[1][2*p+1][2], acc[1][2*p+1][3],
                         af[1][0], af[1][1], af[1][2], af[1][3], bf[2], bf[3]);
            }
        }
        __syncthreads();
    }

    // epilogue
#pragma unroll
    for (int mt = 0; mt < 2; mt++)
#pragma unroll
    for (int nt = 0; nt < 8; nt++) {
        const int row0 = rowBase + wm + mt * 16 + (lane >> 2);
        const int col  = colBase + wn + nt * 8 + 2 * (lane & 3);
        if (MODE == 0) {
            *(float2*)&C[(size_t)row0 * N + col] =
                make_float2(acc[mt][nt][0], acc[mt][nt][1]);
            *(float2*)&C[(size_t)(row0 + 8) * N + col] =
                make_float2(acc[mt][nt][2], acc[mt][nt][3]);
        } else if (MODE == 2) {
            *(float2*)&C[(size_t)row0 * N + col] = make_float2(
                __uint_as_float(f2tf(0.125f * acc[mt][nt][0])),
                __uint_as_float(f2tf(0.125f * acc[mt][nt][1])));
            *(float2*)&C[(size_t)(row0 + 8) * N + col] = make_float2(
                __uint_as_float(f2tf(0.125f * acc[mt][nt][2])),
                __uint_as_float(f2tf(0.125f * acc[mt][nt][3])));
        } else {
            const int g = col >> 6, d = col & 63;
            {
                const int bb2 = row0 >> 11, ss = row0 & (kS - 1);
                *(float2*)&C[((((size_t)bb2 * kNKV + g) * kS + ss) << 6) + d] =
                    make_float2(acc[mt][nt][0], acc[mt][nt][1]);
            }
            {
                const int r1 = row0 + 8;
                const int bb2 = r1 >> 11, ss = r1 & (kS - 1);
                *(float2*)&C[((((size_t)bb2 * kNKV + g) * kS + ss) << 6) + d] =
                    make_float2(acc[mt][nt][2], acc[mt][nt][3]);
            }
        }
    }
}

// ---------------------------------------------------------------------------
// Causal GQA flash attention, tf32 mma.
// 8 warps x 16 q-rows = 128 rows/block; 64-key tiles; grid = (S/128, B*NH).
// Q read as pre-scaled tf32 bits; K/V converted once per element at smem
// store; S B-frags via ldmatrix; P->A frag via lane shuffles; ctx written
// as tf32 bits for the O-projection.
// smem: Ks[64][68] | Vs[64][72] (Q staged in same region before main loop)
// ---------------------------------------------------------------------------
namespace {
constexpr int kKsStr = 68, kVsStr = 72;
constexpr int kAttSmem = (64 * kKsStr + 64 * kVsStr) * 4;   // 35840 bytes
}

__global__ __launch_bounds__(256)
void attn_mma(const float* __restrict__ Qt, const float* __restrict__ Kc,
              const float* __restrict__ Vc, float* __restrict__ ctx)
{
    extern __shared__ uint32_t smu[];
    uint32_t* Ks = smu;                       // [64][68] tf32 bits
    uint32_t* Vs = smu + 64 * kKsStr;         // [64][72] tf32 bits
    uint32_t* Qs = smu;                       // staging [128][68]
    const uint32_t smBase = smem_u32(smu);

    const int t    = threadIdx.x;
    const int lane = t & 31;
    const int wid  = t >> 5;
    const int bh = blockIdx.y;
    const int b  = bh >> 5;
    const int h  = bh & 31;
    const int g  = h >> 2;
    const int qb = blockIdx.x * 128;
    const int wm = wid * 16;

    // ---- stage Q (tf32 bits) -> smem -> ldmatrix fragments
    const uint32_t* qg = (const uint32_t*)Qt + ((size_t)(b * kS + qb)) * kDout + h * kHD;
#pragma unroll
    for (int i = 0; i < 8; i++) {
        const int v = t + i * 256;
        const int r = v >> 4, c4 = (v & 15) * 4;
        *(uint4*)&Qs[r * kKsStr + c4] = *(const uint4*)&qg[(size_t)r * kDout + c4];
    }
    __syncthreads();
    uint32_t qf[8][4];
    {
        const uint32_t qOff = smBase +
            ((wm + (lane & 7) + ((lane >> 3) & 1) * 8) * kKsStr + (lane >> 4) * 4) * 4;
#pragma unroll
        for (int ks = 0; ks < 8; ks++) LDMX4(qf[ks], qOff + ks * 8 * 4);
    }
    __syncthreads();

    float oacc[8][4] = {};
    float m0 = -1e30f, m1 = -1e30f, l0 = 0.f, l1 = 0.f;

    const float* kg = Kc + ((size_t)(b * kNKV + g)) * kS * kHD;
    const float* vg = Vc + ((size_t)(b * kNKV + g)) * kS * kHD;

    const uint32_t kOff = smBase +
        ((((lane >> 4) & 1) * 8 + (lane & 7)) * kKsStr + ((lane >> 3) & 1) * 4) * 4;
    const int s0 = (lane & ~3) | ((lane & 3) >> 1);
    const int s1 = s0 + 2;
    const bool oddk = lane & 1;

    const int ntk = blockIdx.x * 2 + 2;
    for (int kt = 0; kt < ntk; kt++) {
        // cooperative load + single tf32 convert per element
#pragma unroll
        for (int i = 0; i < 4; i++) {
            const int v = t + i * 256;
            const int key = v >> 4, c4 = (v & 15) * 4;
            const float4 kk = *(const float4*)&kg[(size_t)(kt * 64 + key) * kHD + c4];
            uint4 ku; ku.x = f2tf(kk.x); ku.y = f2tf(kk.y); ku.z = f2tf(kk.z); ku.w = f2tf(kk.w);
            *(uint4*)&Ks[key * kKsStr + c4] = ku;
            const float4 vv = *(const float4*)&vg[(size_t)(kt * 64 + key) * kHD + c4];
            uint4 vu; vu.x = f2tf(vv.x); vu.y = f2tf(vv.y); vu.z = f2tf(vv.z); vu.w = f2tf(vv.w);
            *(uint4*)&Vs[key * kVsStr + c4] = vu;
        }
        __syncthreads();

        if (kt * 64 <= qb + wm + 15) {          // warp-uniform: any unmasked key?
            // ---- S = Q K^T
            float sacc[8][4] = {};
#pragma unroll
            for (int ks = 0; ks < 8; ks++) {
#pragma unroll
                for (int p = 0; p < 4; p++) {
                    uint32_t bf[4];
                    LDMX4(bf, kOff + (p * 16 * kKsStr + ks * 8) * 4);
                    mma_tf32(sacc[2*p][0], sacc[2*p][1], sacc[2*p][2], sacc[2*p][3],
                             qf[ks][0], qf[ks][1], qf[ks][2], qf[ks][3], bf[0], bf[1]);
                    mma_tf32(sacc[2*p+1][0], sacc[2*p+1][1], sacc[2*p+1][2], sacc[2*p+1][3],
                             qf[ks][0], qf[ks][1], qf[ks][2], qf[ks][3], bf[2], bf[3]);
                }
            }

            // ---- causal mask
            const int r0 = qb + wm + (lane >> 2);
            const int r1 = r0 + 8;
            if (kt * 64 + 63 > qb + wm) {
#pragma unroll
                for (int nt = 0; nt < 8; nt++) {
                    const int c0 = kt * 64 + nt * 8 + 2 * (lane & 3);
                    if (c0     > r0) sacc[nt][0] = -1e30f;
                    if (c0 + 1 > r0) sacc[nt][1] = -1e30f;
                    if (c0     > r1) sacc[nt][2] = -1e30f;
                    if (c0 + 1 > r1) sacc[nt][3] = -1e30f;
                }
            }

            // ---- online softmax
            float t0 = -1e30f, t1 = -1e30f;
#pragma unroll
            for (int nt = 0; nt < 8; nt++) {
                t0 = fmaxf(t0, fmaxf(sacc[nt][0], sacc[nt][1]));
                t1 = fmaxf(t1, fmaxf(sacc[nt][2], sacc[nt][3]));
            }
            t0 = fmaxf(t0, __shfl_xor_sync(0xFFFFFFFFu, t0, 1));
            t0 = fmaxf(t0, __shfl_xor_sync(0xFFFFFFFFu, t0, 2));
            t1 = fmaxf(t1, __shfl_xor_sync(0xFFFFFFFFu, t1, 1));
            t1 = fmaxf(t1, __shfl_xor_sync(0xFFFFFFFFu, t1, 2));
            const float mn0 = fmaxf(m0, t0);
            const float mn1 = fmaxf(m1, t1);
            const float corr0 = __expf(m0 - mn0);
            const float corr1 = __expf(m1 - mn1);
            m0 = mn0; m1 = mn1;

            float rs0 = 0.f, rs1 = 0.f;
#pragma unroll
            for (int nt = 0; nt < 8; nt++) {
                sacc[nt][0] = __expf(sacc[nt][0] - mn0);
                sacc[nt][1] = __expf(sacc[nt][1] - mn0);
                sacc[nt][2] = __expf(sacc[nt][2] - mn1);
                sacc[nt][3] = __expf(sacc[nt][3] - mn1);
                rs0 += sacc[nt][0] + sacc[nt][1];
                rs1 += sacc[nt][2] + sacc[nt][3];
            }
            rs0 += __shfl_xor_sync(0xFFFFFFFFu, rs0, 1);
            rs0 += __shfl_xor_sync(0xFFFFFFFFu, rs0, 2);
            rs1 += __shfl_xor_sync(0xFFFFFFFFu, rs1, 1);
            rs1 += __shfl_xor_sync(0xFFFFFFFFu, rs1, 2);
            l0 = l0 * corr0 + rs0;
            l1 = l1 * corr1 + rs1;

#pragma unroll
            for (int nt = 0; nt < 8; nt++) {
                oacc[nt][0] *= corr0; oacc[nt][1] *= corr0;
                oacc[nt][2] *= corr1; oacc[nt][3] *= corr1;
            }

            // ---- O += P V : P C-frag -> A-frag via shuffles, V frags from smem
#pragma unroll
            for (int ks = 0; ks < 8; ks++) {
                const uint32_t c0 = f2tf(sacc[ks][0]);
                const uint32_t c1 = f2tf(sacc[ks][1]);
                const uint32_t c2 = f2tf(sacc[ks][2]);
                const uint32_t c3 = f2tf(sacc[ks][3]);
                const uint32_t t00 = __shfl_sync(0xFFFFFFFFu, c0, s0);
                const uint32_t t01 = __shfl_sync(0xFFFFFFFFu, c1, s0);
                const uint32_t t10 = __shfl_sync(0xFFFFFFFFu, c2, s0);
                const uint32_t t11 = __shfl_sync(0xFFFFFFFFu, c3, s0);
                const uint32_t u00 = __shfl_sync(0xFFFFFFFFu, c0, s1);
                const uint32_t u01 = __shfl_sync(0xFFFFFFFFu, c1, s1);
                const uint32_t u10 = __shfl_sync(0xFFFFFFFFu, c2, s1);
                const uint32_t u11 = __shfl_sync(0xFFFFFFFFu, c3, s1);
                const uint32_t a0 = oddk ? t01 : t00;
                const uint32_t a1 = oddk ? t11 : t10;
                const uint32_t a2 = oddk ? u01 : u00;
                const uint32_t a3 = oddk ? u11 : u10;
                const uint32_t* vp = Vs + (ks * 8 + (lane & 3)) * kVsStr + (lane >> 2);
#pragma unroll
                for (int nt = 0; nt < 8; nt++) {
                    const uint32_t b0 = vp[nt * 8];
                    const uint32_t b1 = vp[4 * kVsStr + nt * 8];
                    mma_tf32(oacc[nt][0], oacc[nt][1], oacc[nt][2], oacc[nt][3],
                             a0, a1, a2, a3, b0, b1);
                }
            }
        }
        __syncthreads();
    }

    // ---- epilogue: write ctx as tf32 bits (consumed by O-proj GEMM)
    const float inv0 = 1.f / l0;
    const float inv1 = 1.f / l1;
    float* og = ctx + ((size_t)(b * kS + qb + wm + (lane >> 2))) * kDout + h * kHD;
    const int cbase = 2 * (lane & 3);
#pragma unroll
    for (int nt = 0; nt < 8; nt++) {
        const int col = nt * 8 + cbase;
        *(float2*)&og[col] = make_float2(
            __uint_as_float(f2tf(oacc[nt][0] * inv0)),
            __uint_as_float(f2tf(oacc[nt][1] * inv0)));
        *(float2*)&og[(size_t)8 * kDout + col] = make_float2(
            __uint_as_float(f2tf(oacc[nt][2] * inv1)),
            __uint_as_float(f2tf(oacc[nt][3] * inv1)));
    }
}

// ---------------------------------------------------------------------------
extern "C" void kernel_launch(void* const* d_in, const int* in_sizes, int n_in,
                              void* d_out, int out_size)
{
    const float* x  = (const float*)d_in[0];
    const float* Wq = (const float*)d_in[1];
    const float* Wk = (const float*)d_in[2];
    const float* Wv = (const float*)d_in[3];
    const float* Wo = (const float*)d_in[4];

    float* out    = (float*)d_out;
    float* keys   = out + (size_t)kM * kDout;
    float* values = keys + (size_t)kB * kNKV * kS * kHD;

    float *Qp, *Cxp;
    uint32_t *xT, *wqT, *wkT, *wvT, *woT;
    cudaGetSymbolAddress((void**)&Qp,  g_Q);
    cudaGetSymbolAddress((void**)&Cxp, g_ctx);
    cudaGetSymbolAddress((void**)&xT,  g_xT);
    cudaGetSymbolAddress((void**)&wqT, g_wqT);
    cudaGetSymbolAddress((void**)&wkT, g_wkT);
    cudaGetSymbolAddress((void**)&wvT, g_wvT);
    cudaGetSymbolAddress((void**)&woT, g_woT);

    cudaFuncSetAttribute(gemm_tf32<0>, cudaFuncAttributeMaxDynamicSharedMemorySize, kGemmSmem);
    cudaFuncSetAttribute(gemm_tf32<1>, cudaFuncAttributeMaxDynamicSharedMemorySize, kGemmSmem);
    cudaFuncSetAttribute(gemm_tf32<2>, cudaFuncAttributeMaxDynamicSharedMemorySize, kGemmSmem);

    // one-time tf32-bit conversion of x and weights (idempotent, deterministic)
    cvt_tf32<<<1024, 256>>>((const float4*)x,  (uint4*)xT,  kM * kDin / 4);
    cvt_tf32<<<1024, 256>>>((const float4*)Wq, (uint4*)wqT, kDout * kDin / 4);
    cvt_tf32<<<512,  256>>>((const float4*)Wk, (uint4*)wkT, kDkv * kDin / 4);
    cvt_tf32<<<512,  256>>>((const float4*)Wv, (uint4*)wvT, kDkv * kDin / 4);
    cvt_tf32<<<1024, 256>>>((const float4*)Wo, (uint4*)woT, kDin * kDout / 4);

    // Projections
    gemm_tf32<2><<<dim3(kDout / BN, kM / BM), 256, kGemmSmem>>>(xT, wqT, Qp,     kM, kDout, kDin);
    gemm_tf32<1><<<dim3(kDkv  / BN, kM / BM), 256, kGemmSmem>>>(xT, wkT, keys,   kM, kDkv,  kDin);
    gemm_tf32<1><<<dim3(kDkv  / BN, kM / BM), 256, kGemmSmem>>>(xT, wvT, values, kM, kDkv,  kDin);

    // Causal GQA attention
    attn_mma<<<dim3(kS / 128, kB * kNH), 256, kAttSmem>>>(Qp, keys, values, Cxp);

    // Output projection (ctx already tf32 bits)
    gemm_tf32<0><<<dim3(kDout / BN, kM / BM), 256, kGemmSmem>>>(
        (const uint32_t*)Cxp, woT, out, kM, kDout, kDin);
}

// round 5
// speedup vs baseline: 4.3350x; 1.0386x over previous
#include <cuda_runtime.h>
#include <cstdint>
#include <cstddef>

// ---------------------------------------------------------------------------
// GroupedQueryAttention: B=2, S=2048, D_IN=2048, 32 heads x 64, 8 KV groups
// d_out: out [2,2048,2048] | keys [2,8,2048,64] | values [2,8,2048,64]
// tf32 mma.sync everywhere. Operands pre-converted to tf32 bits exactly once.
// GEMM: 3-stage cp.async pipeline, 1 barrier/chunk, L2-grouped raster.
// Attention: cp.async double-buffered tf32 K/V tiles, exp2-domain softmax.
// ---------------------------------------------------------------------------

namespace {
constexpr int kB    = 2;
constexpr int kS    = 2048;
constexpr int kDin  = 2048;
constexpr int kDout = 2048;
constexpr int kNH   = 32;
constexpr int kNKV  = 8;
constexpr int kHD   = 64;
constexpr int kM    = kB * kS;       // 4096
constexpr int kDkv  = kNKV * kHD;    // 512
constexpr float kQScale = 0.125f * 1.4426950408889634f;   // 1/sqrt(64) * log2(e)
}

// Scratch (device globals: no allocation allowed)
__device__ float    g_Q  [(size_t)kM * kDout];     // tf32 bits, pre-scaled
__device__ float    g_ctx[(size_t)kM * kDout];     // tf32 bits
__device__ uint32_t g_xT [(size_t)kM    * kDin];
__device__ uint32_t g_wqT[(size_t)kDout * kDin];
__device__ uint32_t g_wkT[(size_t)kDkv  * kDin];
__device__ uint32_t g_wvT[(size_t)kDkv  * kDin];
__device__ uint32_t g_woT[(size_t)kDin  * kDout];
__device__ uint32_t g_kT [(size_t)kB * kNKV * kS * kHD];   // tf32 keys
__device__ uint32_t g_vT [(size_t)kB * kNKV * kS * kHD];   // tf32 values

// ------------------------- helpers -----------------------------------------
__device__ __forceinline__ uint32_t smem_u32(const void* p) {
    uint32_t a;
    asm("{ .reg .u64 t; cvta.to.shared.u64 t, %1; cvt.u32.u64 %0, t; }" : "=r"(a) : "l"(p));
    return a;
}
__device__ __forceinline__ uint32_t f2tf(float f) {
    uint32_t r;
    asm("cvt.rna.tf32.f32 %0, %1;" : "=r"(r) : "f"(f));
    return r;
}
__device__ __forceinline__ float fexp2(float x) {
    float r;
    asm("ex2.approx.f32 %0, %1;" : "=f"(r) : "f"(x));
    return r;
}
__device__ __forceinline__ void mma_tf32(float& c0, float& c1, float& c2, float& c3,
                                         uint32_t a0, uint32_t a1, uint32_t a2, uint32_t a3,
                                         uint32_t b0, uint32_t b1) {
    asm volatile(
        "mma.sync.aligned.m16n8k8.row.col.f32.tf32.tf32.f32 "
        "{%0,%1,%2,%3}, {%4,%5,%6,%7}, {%8,%9}, {%0,%1,%2,%3};"
        : "+f"(c0), "+f"(c1), "+f"(c2), "+f"(c3)
        : "r"(a0), "r"(a1), "r"(a2), "r"(a3), "r"(b0), "r"(b1));
}
#define LDMX4(r, addr)                                                        \
    asm volatile("ldmatrix.sync.aligned.m8n8.x4.shared.b16 {%0,%1,%2,%3}, [%4];" \
        : "=r"((r)[0]), "=r"((r)[1]), "=r"((r)[2]), "=r"((r)[3]) : "r"(addr))
__device__ __forceinline__ void cp_async16(uint32_t dst, const void* src) {
    asm volatile("cp.async.cg.shared.global [%0], [%1], 16;" :: "r"(dst), "l"(src));
}
#define CP_COMMIT() asm volatile("cp.async.commit_group;" ::: "memory")
#define CP_WAIT(n)  asm volatile("cp.async.wait_group %0;" :: "n"(n) : "memory")

// ---------------------------------------------------------------------------
// fp32 -> tf32-bit conversion pass (vectorized)
// ---------------------------------------------------------------------------
__global__ __launch_bounds__(256)
void cvt_tf32(const float4* __restrict__ in, uint4* __restrict__ out, int n4)
{
    int i = blockIdx.x * blockDim.x + threadIdx.x;
    const int stride = gridDim.x * blockDim.x;
    for (; i < n4; i += stride) {
        const float4 v = in[i];
        uint4 o;
        o.x = f2tf(v.x); o.y = f2tf(v.y); o.z = f2tf(v.z); o.w = f2tf(v.w);
        out[i] = o;
    }
}

// ---------------------------------------------------------------------------
// tf32 GEMM: C[m,n] = sum_k A[m,k]*B[n,k]  (pre-converted tf32-bit operands)
// BM=BN=128, BK=32, 256 threads, warp tile 32x64, ldmatrix fragments.
// 3-stage cp.async pipeline, ONE __syncthreads per chunk, grouped raster.
// MODE 0: fp32 C.  MODE 1: KV-cache fp32 C + tf32 Ct.  MODE 2: tf32 bits of
// (kQScale * acc).
// ---------------------------------------------------------------------------
namespace {
constexpr int BM = 128, BN = 128, BK = 32, STR = 36;
constexpr int kStageU32  = (BM + BN) * STR;          // 9216 u32 = 36864 B
constexpr int kGemmSmem  = 3 * kStageU32 * 4;        // 110592 B
}

template <int MODE>
__global__ __launch_bounds__(256, 2)
void gemm_tf32(const uint32_t* __restrict__ A, const uint32_t* __restrict__ Bw,
               float* __restrict__ C, uint32_t* __restrict__ Ct,
               int M, int N, int K)
{
    extern __shared__ uint32_t smu[];
    const uint32_t smBase = smem_u32(smu);

    const int t    = threadIdx.x;
    const int lane = t & 31;
    const int wid  = t >> 5;
    const int wm   = (wid & 3) * 32;
    const int wn   = (wid >> 2) * 64;

    // grouped raster: groups of 8 row-blocks share B columns for L2 locality
    const int nbn = gridDim.x, nbm = gridDim.y;
    const int bid = blockIdx.y * nbn + blockIdx.x;
    const int ning = 8 * nbn;
    const int gid  = bid / ning;
    const int fm   = gid * 8;
    const int gsz  = min(8, nbm - fm);
    const int r    = bid % ning;
    const int rowBase = (fm + r % gsz) * BM;
    const int colBase = (r / gsz) * BN;

    float acc[2][8][4] = {};

    auto load_tile = [&](int kt, int st) {
        const uint32_t* Ag = A  + (size_t)rowBase * K + kt * BK;
        const uint32_t* Bg = Bw + (size_t)colBase * K + kt * BK;
        const uint32_t dst = smBase + st * kStageU32 * 4;
#pragma unroll
        for (int i = 0; i < 4; i++) {
            const int v = t + i * 256;
            const int rr = v >> 3, c4 = (v & 7) * 4;
            cp_async16(dst + (rr * STR + c4) * 4, Ag + (size_t)rr * K + c4);
        }
#pragma unroll
        for (int i = 0; i < 4; i++) {
            const int v = t + i * 256;
            const int rr = v >> 3, c4 = (v & 7) * 4;
            cp_async16(dst + (BM * STR + rr * STR + c4) * 4, Bg + (size_t)rr * K + c4);
        }
        CP_COMMIT();
    };

    const uint32_t aOff = ((wm + (lane & 7) + ((lane >> 3) & 1) * 8) * STR + (lane >> 4) * 4) * 4;
    const uint32_t bOff = ((wn + ((lane >> 4) & 1) * 8 + (lane & 7)) * STR + ((lane >> 3) & 1) * 4) * 4;

    const int NC = K / BK;
    load_tile(0, 0);
    load_tile(1, 1);

    int st = 0;   // stage of chunk c
    for (int c = 0; c < NC; c++) {
        if (c + 1 < NC) { CP_WAIT(1); } else { CP_WAIT(0); }
        __syncthreads();
        if (c + 2 < NC) {
            int st2 = st + 2; if (st2 >= 3) st2 -= 3;
            load_tile(c + 2, st2);
        }

        const uint32_t ba = smBase + st * kStageU32 * 4;
        const uint32_t bb = ba + BM * STR * 4;
#pragma unroll
        for (int ks = 0; ks < 4; ks++) {
            uint32_t af[2][4];
            LDMX4(af[0], ba + aOff + (ks * 8) * 4);
            LDMX4(af[1], ba + aOff + (16 * STR + ks * 8) * 4);
#pragma unroll
            for (int p = 0; p < 4; p++) {
                uint32_t bf[4];
                LDMX4(bf, bb + bOff + (p * 16 * STR + ks * 8) * 4);
                mma_tf32(acc[0][2*p][0], acc[0][2*p][1], acc[0][2*p][2], acc[0][2*p][3],
                         af[0][0], af[0][1], af[0][2], af[0][3], bf[0], bf[1]);
                mma_tf32(acc[1][2*p][0], acc[1][2*p][1], acc[1][2*p][2], acc[1][2*p][3],
                         af[1][0], af[1][1], af[1][2], af[1][3], bf[0], bf[1]);
                mma_tf32(acc[0][2*p+1][0], acc[0][2*p+1][1], acc[0][2*p+1][2], acc[0][2*p+1][3],
                         af[0][0], af[0][1], af[0][2], af[0][3], bf[2], bf[3]);
                mma_tf32(acc[1][2*p+1][0], acc[1][2*p+1][1], acc[1][2*p+1][2], acc[1][2*p+1][3],
                         af[1][0], af[1][1], af[1][2], af[1][3], bf[2], bf[3]);
            }
        }
        if (++st == 3) st = 0;
    }

    // epilogue
#pragma unroll
    for (int mt = 0; mt < 2; mt++)
#pragma unroll
    for (int nt = 0; nt < 8; nt++) {
        const int row0 = rowBase + wm + mt * 16 + (lane >> 2);
        const int col  = colBase + wn + nt * 8 + 2 * (lane & 3);
        if (MODE == 0) {
            *(float2*)&C[(size_t)row0 * N + col] =
                make_float2(acc[mt][nt][0], acc[mt][nt][1]);
            *(float2*)&C[(size_t)(row0 + 8) * N + col] =
                make_float2(acc[mt][nt][2], acc[mt][nt][3]);
        } else if (MODE == 2) {
            *(float2*)&C[(size_t)row0 * N + col] = make_float2(
                __uint_as_float(f2tf(kQScale * acc[mt][nt][0])),
                __uint_as_float(f2tf(kQScale * acc[mt][nt][1])));
            *(float2*)&C[(size_t)(row0 + 8) * N + col] = make_float2(
                __uint_as_float(f2tf(kQScale * acc[mt][nt][2])),
                __uint_as_float(f2tf(kQScale * acc[mt][nt][3])));
        } else {
            const int g = col >> 6, d = col & 63;
            {
                const int bb2 = row0 >> 11, ss = row0 & (kS - 1);
                const size_t o = ((((size_t)bb2 * kNKV + g) * kS + ss) << 6) + d;
                *(float2*)&C[o] = make_float2(acc[mt][nt][0], acc[mt][nt][1]);
                Ct[o]     = f2tf(acc[mt][nt][0]);
                Ct[o + 1] = f2tf(acc[mt][nt][1]);
            }
            {
                const int r1 = row0 + 8;
                const int bb2 = r1 >> 11, ss = r1 & (kS - 1);
                const size_t o = ((((size_t)bb2 * kNKV + g) * kS + ss) << 6) + d;
                *(float2*)&C[o] = make_float2(acc[mt][nt][2], acc[mt][nt][3]);
                Ct[o]     = f2tf(acc[mt][nt][2]);
                Ct[o + 1] = f2tf(acc[mt][nt][3]);
            }
        }
    }
}

// ---------------------------------------------------------------------------
// Causal GQA flash attention, tf32 mma.
// 8 warps x 16 q-rows = 128 rows/block; 64-key tiles; grid = (S/128, B*NH).
// K/V tiles cp.async'd (already tf32 bits) into double-buffered smem.
// Softmax in exp2 domain (log2e folded into Q scale).
// smem per buffer: Ks[64][68] | Vs[64][72]; two buffers.
// ---------------------------------------------------------------------------
namespace {
constexpr int kKsStr = 68, kVsStr = 72;
constexpr int kAttBufU32 = 64 * kKsStr + 64 * kVsStr;       // 8960 u32 = 35840 B
constexpr int kAttSmem   = 2 * kAttBufU32 * 4;              // 71680 B
}

__global__ __launch_bounds__(256, 2)
void attn_mma(const uint32_t* __restrict__ Qt, const uint32_t* __restrict__ KT,
              const uint32_t* __restrict__ VT, float* __restrict__ ctx)
{
    extern __shared__ uint32_t smu[];
    const uint32_t smBase = smem_u32(smu);

    const int t    = threadIdx.x;
    const int lane = t & 31;
    const int wid  = t >> 5;
    const int bh = blockIdx.y;
    const int b  = bh >> 5;
    const int h  = bh & 31;
    const int g  = h >> 2;
    const int qb = blockIdx.x * 128;
    const int wm = wid * 16;

    // ---- stage Q (tf32 bits) -> smem -> ldmatrix fragments
    const uint32_t* qg = Qt + ((size_t)(b * kS + qb)) * kDout + h * kHD;
#pragma unroll
    for (int i = 0; i < 8; i++) {
        const int v = t + i * 256;
        const int rr = v >> 4, c4 = (v & 15) * 4;
        *(uint4*)&smu[rr * kKsStr + c4] = *(const uint4*)&qg[(size_t)rr * kDout + c4];
    }
    __syncthreads();
    uint32_t qf[8][4];
    {
        const uint32_t qOff = smBase +
            ((wm + (lane & 7) + ((lane >> 3) & 1) * 8) * kKsStr + (lane >> 4) * 4) * 4;
#pragma unroll
        for (int ks = 0; ks < 8; ks++) LDMX4(qf[ks], qOff + ks * 8 * 4);
    }
    __syncthreads();

    float oacc[8][4] = {};
    float m0 = -1e30f, m1 = -1e30f, l0 = 0.f, l1 = 0.f;

    const uint32_t* kg = KT + ((size_t)(b * kNKV + g)) * kS * kHD;
    const uint32_t* vg = VT + ((size_t)(b * kNKV + g)) * kS * kHD;

    auto load_tile = [&](int kt, int buf) {
        const uint32_t dstK = smBase + buf * kAttBufU32 * 4;
        const uint32_t dstV = dstK + 64 * kKsStr * 4;
#pragma unroll
        for (int i = 0; i < 4; i++) {
            const int v = t + i * 256;
            const int key = v >> 4, c4 = (v & 15) * 4;
            cp_async16(dstK + (key * kKsStr + c4) * 4, kg + (size_t)(kt * 64 + key) * kHD + c4);
            cp_async16(dstV + (key * kVsStr + c4) * 4, vg + (size_t)(kt * 64 + key) * kHD + c4);
        }
        CP_COMMIT();
    };

    const uint32_t kOffRel =
        ((((lane >> 4) & 1) * 8 + (lane & 7)) * kKsStr + ((lane >> 3) & 1) * 4) * 4;
    const int s0 = (lane & ~3) | ((lane & 3) >> 1);
    const int s1 = s0 + 2;
    const bool oddk = lane & 1;

    const int ntk = blockIdx.x * 2 + 2;
    load_tile(0, 0);

    for (int kt = 0; kt < ntk; kt++) {
        const int buf = kt & 1;
        if (kt + 1 < ntk) { load_tile(kt + 1, buf ^ 1); CP_WAIT(1); }
        else              { CP_WAIT(0); }
        __syncthreads();

        if (kt * 64 <= qb + wm + 15) {          // warp-uniform: any unmasked key?
            const uint32_t kBase = smBase + buf * kAttBufU32 * 4 + kOffRel;
            // ---- S = Q K^T  (exp2 domain: Q pre-scaled by 0.125*log2e)
            float sacc[8][4] = {};
#pragma unroll
            for (int ks = 0; ks < 8; ks++) {
#pragma unroll
                for (int p = 0; p < 4; p++) {
                    uint32_t bf[4];
                    LDMX4(bf, kBase + (p * 16 * kKsStr + ks * 8) * 4);
                    mma_tf32(sacc[2*p][0], sacc[2*p][1], sacc[2*p][2], sacc[2*p][3],
                             qf[ks][0], qf[ks][1], qf[ks][2], qf[ks][3], bf[0], bf[1]);
                    mma_tf32(sacc[2*p+1][0], sacc[2*p+1][1], sacc[2*p+1][2], sacc[2*p+1][3],
                             qf[ks][0], qf[ks][1], qf[ks][2], qf[ks][3], bf[2], bf[3]);
                }
            }

            // ---- causal mask
            const int r0 = qb + wm + (lane >> 2);
            const int r1 = r0 + 8;
            if (kt * 64 + 63 > qb + wm) {
#pragma unroll
                for (int nt = 0; nt < 8; nt++) {
                    const int c0 = kt * 64 + nt * 8 + 2 * (lane & 3);
                    if (c0     > r0) sacc[nt][0] = -1e30f;
                    if (c0 + 1 > r0) sacc[nt][1] = -1e30f;
                    if (c0     > r1) sacc[nt][2] = -1e30f;
                    if (c0 + 1 > r1) sacc[nt][3] = -1e30f;
                }
            }

            // ---- online softmax (base-2)
            float t0 = -1e30f, t1 = -1e30f;
#pragma unroll
            for (int nt = 0; nt < 8; nt++) {
                t0 = fmaxf(t0, fmaxf(sacc[nt][0], sacc[nt][1]));
                t1 = fmaxf(t1, fmaxf(sacc[nt][2], sacc[nt][3]));
            }
            t0 = fmaxf(t0, __shfl_xor_sync(0xFFFFFFFFu, t0, 1));
            t0 = fmaxf(t0, __shfl_xor_sync(0xFFFFFFFFu, t0, 2));
            t1 = fmaxf(t1, __shfl_xor_sync(0xFFFFFFFFu, t1, 1));
            t1 = fmaxf(t1, __shfl_xor_sync(0xFFFFFFFFu, t1, 2));
            const float mn0 = fmaxf(m0, t0);
            const float mn1 = fmaxf(m1, t1);
            const float corr0 = fexp2(m0 - mn0);
            const float corr1 = fexp2(m1 - mn1);
            m0 = mn0; m1 = mn1;

            float rs0 = 0.f, rs1 = 0.f;
#pragma unroll
            for (int nt = 0; nt < 8; nt++) {
                sacc[nt][0] = fexp2(sacc[nt][0] - mn0);
                sacc[nt][1] = fexp2(sacc[nt][1] - mn0);
                sacc[nt][2] = fexp2(sacc[nt][2] - mn1);
                sacc[nt][3] = fexp2(sacc[nt][3] - mn1);
                rs0 += sacc[nt][0] + sacc[nt][1];
                rs1 += sacc[nt][2] + sacc[nt][3];
            }
            rs0 += __shfl_xor_sync(0xFFFFFFFFu, rs0, 1);
            rs0 += __shfl_xor_sync(0xFFFFFFFFu, rs0, 2);
            rs1 += __shfl_xor_sync(0xFFFFFFFFu, rs1, 1);
            rs1 += __shfl_xor_sync(0xFFFFFFFFu, rs1, 2);
            l0 = l0 * corr0 + rs0;
            l1 = l1 * corr1 + rs1;

#pragma unroll
            for (int nt = 0; nt < 8; nt++) {
                oacc[nt][0] *= corr0; oacc[nt][1] *= corr0;
                oacc[nt][2] *= corr1; oacc[nt][3] *= corr1;
            }

            // ---- O += P V : P C-frag -> A-frag via shuffles, V frags from smem
            const uint32_t* vb = smu + buf * kAttBufU32 + 64 * kKsStr;
#pragma unroll
            for (int ks = 0; ks < 8; ks++) {
                const uint32_t c0 = f2tf(sacc[ks][0]);
                const uint32_t c1 = f2tf(sacc[ks][1]);
                const uint32_t c2 = f2tf(sacc[ks][2]);
                const uint32_t c3 = f2tf(sacc[ks][3]);
                const uint32_t t00 = __shfl_sync(0xFFFFFFFFu, c0, s0);
                const uint32_t t01 = __shfl_sync(0xFFFFFFFFu, c1, s0);
                const uint32_t t10 = __shfl_sync(0xFFFFFFFFu, c2, s0);
                const uint32_t t11 = __shfl_sync(0xFFFFFFFFu, c3, s0);
                const uint32_t u00 = __shfl_sync(0xFFFFFFFFu, c0, s1);
                const uint32_t u01 = __shfl_sync(0xFFFFFFFFu, c1, s1);
                const uint32_t u10 = __shfl_sync(0xFFFFFFFFu, c2, s1);
                const uint32_t u11 = __shfl_sync(0xFFFFFFFFu, c3, s1);
                const uint32_t a0 = oddk ? t01 : t00;
                const uint32_t a1 = oddk ? t11 : t10;
                const uint32_t a2 = oddk ? u01 : u00;
                const uint32_t a3 = oddk ? u11 : u10;
                const uint32_t* vp = vb + (ks * 8 + (lane & 3)) * kVsStr + (lane >> 2);
#pragma unroll
                for (int nt = 0; nt < 8; nt++) {
                    const uint32_t b0 = vp[nt * 8];
                    const uint32_t b1 = vp[4 * kVsStr + nt * 8];
                    mma_tf32(oacc[nt][0], oacc[nt][1], oacc[nt][2], oacc[nt][3],
                             a0, a1, a2, a3, b0, b1);
                }
            }
        }
        __syncthreads();
    }

    // ---- epilogue: write ctx as tf32 bits (consumed by O-proj GEMM)
    const float inv0 = 1.f / l0;
    const float inv1 = 1.f / l1;
    float* og = ctx + ((size_t)(b * kS + qb + wm + (lane >> 2))) * kDout + h * kHD;
    const int cbase = 2 * (lane & 3);
#pragma unroll
    for (int nt = 0; nt < 8; nt++) {
        const int col = nt * 8 + cbase;
        *(float2*)&og[col] = make_float2(
            __uint_as_float(f2tf(oacc[nt][0] * inv0)),
            __uint_as_float(f2tf(oacc[nt][1] * inv0)));
        *(float2*)&og[(size_t)8 * kDout + col] = make_float2(
            __uint_as_float(f2tf(oacc[nt][2] * inv1)),
            __uint_as_float(f2tf(oacc[nt][3] * inv1)));
    }
}

// ---------------------------------------------------------------------------
extern "C" void kernel_launch(void* const* d_in, const int* in_sizes, int n_in,
                              void* d_out, int out_size)
{
    const float* x  = (const float*)d_in[0];
    const float* Wq = (const float*)d_in[1];
    const float* Wk = (const float*)d_in[2];
    const float* Wv = (const float*)d_in[3];
    const float* Wo = (const float*)d_in[4];

    float* out    = (float*)d_out;
    float* keys   = out + (size_t)kM * kDout;
    float* values = keys + (size_t)kB * kNKV * kS * kHD;

    float *Qp, *Cxp;
    uint32_t *xT, *wqT, *wkT, *wvT, *woT, *kT, *vT;
    cudaGetSymbolAddress((void**)&Qp,  g_Q);
    cudaGetSymbolAddress((void**)&Cxp, g_ctx);
    cudaGetSymbolAddress((void**)&xT,  g_xT);
    cudaGetSymbolAddress((void**)&wqT, g_wqT);
    cudaGetSymbolAddress((void**)&wkT, g_wkT);
    cudaGetSymbolAddress((void**)&wvT, g_wvT);
    cudaGetSymbolAddress((void**)&woT, g_woT);
    cudaGetSymbolAddress((void**)&kT,  g_kT);
    cudaGetSymbolAddress((void**)&vT,  g_vT);

    cudaFuncSetAttribute(gemm_tf32<0>, cudaFuncAttributeMaxDynamicSharedMemorySize, kGemmSmem);
    cudaFuncSetAttribute(gemm_tf32<1>, cudaFuncAttributeMaxDynamicSharedMemorySize, kGemmSmem);
    cudaFuncSetAttribute(gemm_tf32<2>, cudaFuncAttributeMaxDynamicSharedMemorySize, kGemmSmem);
    cudaFuncSetAttribute(attn_mma,     cudaFuncAttributeMaxDynamicSharedMemorySize, kAttSmem);

    // one-time tf32-bit conversion of x and weights
    cvt_tf32<<<1024, 256>>>((const float4*)x,  (uint4*)xT,  kM * kDin / 4);
    cvt_tf32<<<1024, 256>>>((const float4*)Wq, (uint4*)wqT, kDout * kDin / 4);
    cvt_tf32<<<512,  256>>>((const float4*)Wk, (uint4*)wkT, kDkv * kDin / 4);
    cvt_tf32<<<512,  256>>>((const float4*)Wv, (uint4*)wvT, kDkv * kDin / 4);
    cvt_tf32<<<1024, 256>>>((const float4*)Wo, (uint4*)woT, kDin * kDout / 4);

    // Projections
    gemm_tf32<2><<<dim3(kDout / BN, kM / BM), 256, kGemmSmem>>>(xT, wqT, Qp,     nullptr, kM, kDout, kDin);
    gemm_tf32<1><<<dim3(kDkv  / BN, kM / BM), 256, kGemmSmem>>>(xT, wkT, keys,   kT,      kM, kDkv,  kDin);
    gemm_tf32<1><<<dim3(kDkv  / BN, kM / BM), 256, kGemmSmem>>>(xT, wvT, values, vT,      kM, kDkv,  kDin);

    // Causal GQA attention
    attn_mma<<<dim3(kS / 128, kB * kNH), 256, kAttSmem>>>(
        (const uint32_t*)Qp, kT, vT, Cxp);

    // Output projection (ctx already tf32 bits)
    gemm_tf32<0><<<dim3(kDout / BN, kM / BM), 256, kGemmSmem>>>(
        (const uint32_t*)Cxp, woT, out, nullptr, kM, kDout, kDin);
}

// round 6
// speedup vs baseline: 8.2939x; 1.9132x over previous
#include <cuda_runtime.h>
#include <cuda_fp16.h>
#include <cstdint>
#include <cstddef>

// ---------------------------------------------------------------------------
// GroupedQueryAttention: B=2, S=2048, D_IN=2048, 32 heads x 64, 8 KV groups
// d_out: out [2,2048,2048] | keys [2,8,2048,64] | values [2,8,2048,64]
// All heavy math via fp16 mma.sync m16n8k16 with fp32 accumulate (same 2^-11
// mantissa as tf32, 2x HMMA rate, half the smem/load traffic).
// ---------------------------------------------------------------------------

namespace {
constexpr int kB    = 2;
constexpr int kS    = 2048;
constexpr int kDin  = 2048;
constexpr int kDout = 2048;
constexpr int kNH   = 32;
constexpr int kNKV  = 8;
constexpr int kHD   = 64;
constexpr int kM    = kB * kS;       // 4096
constexpr int kDkv  = kNKV * kHD;    // 512
constexpr float kQScale = 0.125f * 1.4426950408889634f;   // 1/sqrt(64)*log2(e)
}

// Scratch (device globals: no allocation allowed)
__device__ __half g_Qh  [(size_t)kM * kDout];    // pre-scaled fp16 Q
__device__ __half g_ctxh[(size_t)kM * kDout];    // fp16 ctx
__device__ __half g_xH  [(size_t)kM    * kDin];
__device__ __half g_wqH [(size_t)kDout * kDin];
__device__ __half g_wkH [(size_t)kDkv  * kDin];
__device__ __half g_wvH [(size_t)kDkv  * kDin];
__device__ __half g_woH [(size_t)kDin  * kDout];
__device__ __half g_kH  [(size_t)kB * kNKV * kS * kHD];   // fp16 keys
__device__ __half g_vH  [(size_t)kB * kNKV * kS * kHD];   // fp16 values

// ------------------------- helpers -----------------------------------------
__device__ __forceinline__ uint32_t smem_u32(const void* p) {
    uint32_t a;
    asm("{ .reg .u64 t; cvta.to.shared.u64 t, %1; cvt.u32.u64 %0, t; }" : "=r"(a) : "l"(p));
    return a;
}
__device__ __forceinline__ uint32_t pack_h2(float lo, float hi) {
    uint32_t r;
    asm("cvt.rn.f16x2.f32 %0, %1, %2;" : "=r"(r) : "f"(hi), "f"(lo));
    return r;
}
__device__ __forceinline__ float fexp2(float x) {
    float r;
    asm("ex2.approx.f32 %0, %1;" : "=f"(r) : "f"(x));
    return r;
}
__device__ __forceinline__ void mma_f16(float& c0, float& c1, float& c2, float& c3,
                                        uint32_t a0, uint32_t a1, uint32_t a2, uint32_t a3,
                                        uint32_t b0, uint32_t b1) {
    asm volatile(
        "mma.sync.aligned.m16n8k16.row.col.f32.f16.f16.f32 "
        "{%0,%1,%2,%3}, {%4,%5,%6,%7}, {%8,%9}, {%0,%1,%2,%3};"
        : "+f"(c0), "+f"(c1), "+f"(c2), "+f"(c3)
        : "r"(a0), "r"(a1), "r"(a2), "r"(a3), "r"(b0), "r"(b1));
}
#define LDMX4(r, addr)                                                        \
    asm volatile("ldmatrix.sync.aligned.m8n8.x4.shared.b16 {%0,%1,%2,%3}, [%4];" \
        : "=r"((r)[0]), "=r"((r)[1]), "=r"((r)[2]), "=r"((r)[3]) : "r"(addr))
#define LDMX4T(r, addr)                                                       \
    asm volatile("ldmatrix.sync.aligned.m8n8.x4.trans.shared.b16 {%0,%1,%2,%3}, [%4];" \
        : "=r"((r)[0]), "=r"((r)[1]), "=r"((r)[2]), "=r"((r)[3]) : "r"(addr))
__device__ __forceinline__ void cp_async16(uint32_t dst, const void* src) {
    asm volatile("cp.async.cg.shared.global [%0], [%1], 16;" :: "r"(dst), "l"(src));
}
#define CP_COMMIT() asm volatile("cp.async.commit_group;" ::: "memory")
#define CP_WAIT(n)  asm volatile("cp.async.wait_group %0;" :: "n"(n) : "memory")

// ---------------------------------------------------------------------------
// fp32 -> fp16 conversion pass (vectorized)
// ---------------------------------------------------------------------------
__global__ __launch_bounds__(256)
void cvt_f16(const float4* __restrict__ in, uint2* __restrict__ out, int n4)
{
    int i = blockIdx.x * blockDim.x + threadIdx.x;
    const int stride = gridDim.x * blockDim.x;
    for (; i < n4; i += stride) {
        const float4 v = in[i];
        uint2 o;
        o.x = pack_h2(v.x, v.y);
        o.y = pack_h2(v.z, v.w);
        out[i] = o;
    }
}

// ---------------------------------------------------------------------------
// fp16 GEMM: C[m,n] = sum_k A[m,k]*B[n,k]  (fp16 operands, fp32 accum)
// BM=BN=128, BK=64, 256 threads, warp tile 32x64, m16n8k16 via ldmatrix.
// 3-stage cp.async pipeline, one barrier per chunk, grouped raster.
// MODE 0: fp32 C.  MODE 1: KV-cache fp32 C + fp16 Ch.  MODE 2: fp16 Ch of
// (kQScale * acc), row-major.
// ---------------------------------------------------------------------------
namespace {
constexpr int BM = 128, BN = 128, BK = 64, STR = 72;      // STR in halfs
constexpr int kStageH   = (BM + BN) * STR;                // 18432 halfs
constexpr int kGemmSmem = 3 * kStageH * 2;                // 110592 B
}

template <int MODE>
__global__ __launch_bounds__(256, 2)
void gemm_f16(const __half* __restrict__ A, const __half* __restrict__ Bw,
              float* __restrict__ C, __half* __restrict__ Ch,
              int M, int N, int K)
{
    extern __shared__ __half smh[];
    const uint32_t smBase = smem_u32(smh);

    const int t    = threadIdx.x;
    const int lane = t & 31;
    const int wid  = t >> 5;
    const int wm   = (wid & 3) * 32;
    const int wn   = (wid >> 2) * 64;

    // grouped raster for L2 locality
    const int nbn = gridDim.x, nbm = gridDim.y;
    const int bid = blockIdx.y * nbn + blockIdx.x;
    const int ning = 8 * nbn;
    const int gid  = bid / ning;
    const int fm   = gid * 8;
    const int gsz  = min(8, nbm - fm);
    const int r    = bid % ning;
    const int rowBase = (fm + r % gsz) * BM;
    const int colBase = (r / gsz) * BN;

    float acc[2][8][4] = {};

    auto load_tile = [&](int kt, int st) {
        const __half* Ag = A  + (size_t)rowBase * K + kt * BK;
        const __half* Bg = Bw + (size_t)colBase * K + kt * BK;
        const uint32_t dst = smBase + st * kStageH * 2;
#pragma unroll
        for (int i = 0; i < 4; i++) {                       // A: 128 rows x 8 units
            const int v = t + i * 256;
            const int rr = v >> 3, c8 = (v & 7) * 8;
            cp_async16(dst + (rr * STR + c8) * 2, Ag + (size_t)rr * K + c8);
        }
#pragma unroll
        for (int i = 0; i < 4; i++) {                       // B: 128 rows x 8 units
            const int v = t + i * 256;
            const int rr = v >> 3, c8 = (v & 7) * 8;
            cp_async16(dst + (BM * STR + rr * STR + c8) * 2, Bg + (size_t)rr * K + c8);
        }
        CP_COMMIT();
    };

    // ldmatrix byte offsets
    const uint32_t aOff = ((wm + (lane & 15)) * STR + (lane >> 4) * 8) * 2;
    const uint32_t bOff = ((wn + ((lane >> 4) & 1) * 8 + (lane & 7)) * STR
                           + ((lane >> 3) & 1) * 8) * 2;

    const int NC = K / BK;     // 32 chunks
    load_tile(0, 0);
    load_tile(1, 1);

    int st = 0;
    for (int c = 0; c < NC; c++) {
        if (c + 1 < NC) { CP_WAIT(1); } else { CP_WAIT(0); }
        __syncthreads();
        if (c + 2 < NC) {
            int st2 = st + 2; if (st2 >= 3) st2 -= 3;
            load_tile(c + 2, st2);
        }

        const uint32_t ba = smBase + st * kStageH * 2;
        const uint32_t bb = ba + BM * STR * 2;
#pragma unroll
        for (int ks = 0; ks < 4; ks++) {        // 4 k16 steps per BK=64
            uint32_t af[2][4];
            LDMX4(af[0], ba + aOff + (ks * 16) * 2);
            LDMX4(af[1], ba + aOff + (16 * STR + ks * 16) * 2);
#pragma unroll
            for (int p = 0; p < 4; p++) {
                uint32_t bf[4];
                LDMX4(bf, bb + bOff + (p * 16 * STR + ks * 16) * 2);
                mma_f16(acc[0][2*p][0], acc[0][2*p][1], acc[0][2*p][2], acc[0][2*p][3],
                        af[0][0], af[0][1], af[0][2], af[0][3], bf[0], bf[1]);
                mma_f16(acc[1][2*p][0], acc[1][2*p][1], acc[1][2*p][2], acc[1][2*p][3],
                        af[1][0], af[1][1], af[1][2], af[1][3], bf[0], bf[1]);
                mma_f16(acc[0][2*p+1][0], acc[0][2*p+1][1], acc[0][2*p+1][2], acc[0][2*p+1][3],
                        af[0][0], af[0][1], af[0][2], af[0][3], bf[2], bf[3]);
                mma_f16(acc[1][2*p+1][0], acc[1][2*p+1][1], acc[1][2*p+1][2], acc[1][2*p+1][3],
                        af[1][0], af[1][1], af[1][2], af[1][3], bf[2], bf[3]);
            }
        }
        if (++st == 3) st = 0;
    }

    // epilogue (C frag: c0,c1 = row l/4, col 2(l%4); c2,c3 = row l/4+8)
#pragma unroll
    for (int mt = 0; mt < 2; mt++)
#pragma unroll
    for (int nt = 0; nt < 8; nt++) {
        const int row0 = rowBase + wm + mt * 16 + (lane >> 2);
        const int col  = colBase + wn + nt * 8 + 2 * (lane & 3);
        if (MODE == 0) {
            *(float2*)&C[(size_t)row0 * N + col] =
                make_float2(acc[mt][nt][0], acc[mt][nt][1]);
            *(float2*)&C[(size_t)(row0 + 8) * N + col] =
                make_float2(acc[mt][nt][2], acc[mt][nt][3]);
        } else if (MODE == 2) {
            *(uint32_t*)&Ch[(size_t)row0 * N + col] =
                pack_h2(kQScale * acc[mt][nt][0], kQScale * acc[mt][nt][1]);
            *(uint32_t*)&Ch[(size_t)(row0 + 8) * N + col] =
                pack_h2(kQScale * acc[mt][nt][2], kQScale * acc[mt][nt][3]);
        } else {
            const int g = col >> 6, d = col & 63;
            {
                const int bb2 = row0 >> 11, ss = row0 & (kS - 1);
                const size_t o = ((((size_t)bb2 * kNKV + g) * kS + ss) << 6) + d;
                *(float2*)&C[o] = make_float2(acc[mt][nt][0], acc[mt][nt][1]);
                *(uint32_t*)&Ch[o] = pack_h2(acc[mt][nt][0], acc[mt][nt][1]);
            }
            {
                const int r1 = row0 + 8;
                const int bb2 = r1 >> 11, ss = r1 & (kS - 1);
                const size_t o = ((((size_t)bb2 * kNKV + g) * kS + ss) << 6) + d;
                *(float2*)&C[o] = make_float2(acc[mt][nt][2], acc[mt][nt][3]);
                *(uint32_t*)&Ch[o] = pack_h2(acc[mt][nt][2], acc[mt][nt][3]);
            }
        }
    }
}

// ---------------------------------------------------------------------------
// Causal GQA flash attention, fp16 mma (m16n8k16).
// 8 warps x 16 q-rows = 128 rows/block; 64-key tiles; grid = (S/128, B*NH).
// K/V fp16 tiles via cp.async double buffer.  exp2-domain softmax.
// P re-enters PV mma by direct pairwise packing of the S C-fragments
// (m16n8k16 A-frag == packed C-frag) — no shuffles, no smem round-trip.
// V fragments via ldmatrix.trans.
// smem/buffer: K[64][72] + V[64][72] halfs = 18432 B; two buffers.
// ---------------------------------------------------------------------------
namespace {
constexpr int kAStr = 72;                                  // halfs
constexpr int kAttBufH = 2 * 64 * kAStr;                   // 9216 halfs/buffer
constexpr int kAttSmem = 2 * kAttBufH * 2;                 // 36864 B
}

__global__ __launch_bounds__(256, 2)
void attn_mma(const __half* __restrict__ Qh, const __half* __restrict__ KH,
              const __half* __restrict__ VH, __half* __restrict__ ctx)
{
    extern __shared__ __half smh[];
    const uint32_t smBase = smem_u32(smh);

    const int t    = threadIdx.x;
    const int lane = t & 31;
    const int wid  = t >> 5;
    const int bh = blockIdx.y;
    const int b  = bh >> 5;
    const int h  = bh & 31;
    const int g  = h >> 2;
    const int qb = blockIdx.x * 128;
    const int wm = wid * 16;

    // ---- stage Q (fp16, pre-scaled) -> smem -> ldmatrix A-fragments
    const __half* qg = Qh + ((size_t)(b * kS + qb)) * kDout + h * kHD;
#pragma unroll
    for (int i = 0; i < 4; i++) {
        const int v = t + i * 256;                  // 1024 16B units
        const int rr = v >> 3, c8 = (v & 7) * 8;
        *(uint4*)&smh[rr * kAStr + c8] = *(const uint4*)&qg[(size_t)rr * kDout + c8];
    }
    __syncthreads();
    uint32_t qf[4][4];
    {
        const uint32_t qOff = smBase + ((wm + (lane & 15)) * kAStr + (lane >> 4) * 8) * 2;
#pragma unroll
        for (int ks = 0; ks < 4; ks++) LDMX4(qf[ks], qOff + (ks * 16) * 2);
    }
    __syncthreads();

    float oacc[8][4] = {};
    float m0 = -1e30f, m1 = -1e30f, l0 = 0.f, l1 = 0.f;

    const __half* kg = KH + ((size_t)(b * kNKV + g)) * kS * kHD;
    const __half* vg = VH + ((size_t)(b * kNKV + g)) * kS * kHD;

    auto load_tile = [&](int kt, int buf) {
        const uint32_t dstK = smBase + buf * kAttBufH * 2;
        const uint32_t dstV = dstK + 64 * kAStr * 2;
#pragma unroll
        for (int i = 0; i < 2; i++) {               // K: 512 units
            const int v = t + i * 256;
            const int key = v >> 3, c8 = (v & 7) * 8;
            cp_async16(dstK + (key * kAStr + c8) * 2, kg + (size_t)(kt * 64 + key) * kHD + c8);
        }
#pragma unroll
        for (int i = 0; i < 2; i++) {               // V: 512 units
            const int v = t + i * 256;
            const int key = v >> 3, c8 = (v & 7) * 8;
            cp_async16(dstV + (key * kAStr + c8) * 2, vg + (size_t)(kt * 64 + key) * kHD + c8);
        }
        CP_COMMIT();
    };

    const uint32_t kOffRel =
        ((((lane >> 4) & 1) * 8 + (lane & 7)) * kAStr + ((lane >> 3) & 1) * 8) * 2;
    const uint32_t vOffRel =
        ((((lane >> 3) & 1) * 8 + (lane & 7)) * kAStr + ((lane >> 4) & 1) * 8) * 2;

    const int ntk = blockIdx.x * 2 + 2;
    load_tile(0, 0);

    for (int kt = 0; kt < ntk; kt++) {
        const int buf = kt & 1;
        if (kt + 1 < ntk) { load_tile(kt + 1, buf ^ 1); CP_WAIT(1); }
        else              { CP_WAIT(0); }
        __syncthreads();

        if (kt * 64 <= qb + wm + 15) {              // warp-uniform skip
            const uint32_t kBase = smBase + buf * kAttBufH * 2 + kOffRel;
            const uint32_t vBase = smBase + buf * kAttBufH * 2 + 64 * kAStr * 2 + vOffRel;

            // ---- S = Q K^T
            float sacc[8][4] = {};
#pragma unroll
            for (int ks = 0; ks < 4; ks++) {
#pragma unroll
                for (int p = 0; p < 4; p++) {
                    uint32_t bf[4];
                    LDMX4(bf, kBase + (p * 16 * kAStr + ks * 16) * 2);
                    mma_f16(sacc[2*p][0], sacc[2*p][1], sacc[2*p][2], sacc[2*p][3],
                            qf[ks][0], qf[ks][1], qf[ks][2], qf[ks][3], bf[0], bf[1]);
                    mma_f16(sacc[2*p+1][0], sacc[2*p+1][1], sacc[2*p+1][2], sacc[2*p+1][3],
                            qf[ks][0], qf[ks][1], qf[ks][2], qf[ks][3], bf[2], bf[3]);
                }
            }

            // ---- causal mask
            const int r0 = qb + wm + (lane >> 2);
            const int r1 = r0 + 8;
            if (kt * 64 + 63 > qb + wm) {
#pragma unroll
                for (int nt = 0; nt < 8; nt++) {
                    const int c0 = kt * 64 + nt * 8 + 2 * (lane & 3);
                    if (c0     > r0) sacc[nt][0] = -1e30f;
                    if (c0 + 1 > r0) sacc[nt][1] = -1e30f;
                    if (c0     > r1) sacc[nt][2] = -1e30f;
                    if (c0 + 1 > r1) sacc[nt][3] = -1e30f;
                }
            }

            // ---- online softmax (base 2)
            float t0 = -1e30f, t1 = -1e30f;
#pragma unroll
            for (int nt = 0; nt < 8; nt++) {
                t0 = fmaxf(t0, fmaxf(sacc[nt][0], sacc[nt][1]));
                t1 = fmaxf(t1, fmaxf(sacc[nt][2], sacc[nt][3]));
            }
            t0 = fmaxf(t0, __shfl_xor_sync(0xFFFFFFFFu, t0, 1));
            t0 = fmaxf(t0, __shfl_xor_sync(0xFFFFFFFFu, t0, 2));
            t1 = fmaxf(t1, __shfl_xor_sync(0xFFFFFFFFu, t1, 1));
            t1 = fmaxf(t1, __shfl_xor_sync(0xFFFFFFFFu, t1, 2));
            const float mn0 = fmaxf(m0, t0);
            const float mn1 = fmaxf(m1, t1);
            const float corr0 = fexp2(m0 - mn0);
            const float corr1 = fexp2(m1 - mn1);
            m0 = mn0; m1 = mn1;

            float rs0 = 0.f, rs1 = 0.f;
#pragma unroll
            for (int nt = 0; nt < 8; nt++) {
                sacc[nt][0] = fexp2(sacc[nt][0] - mn0);
                sacc[nt][1] = fexp2(sacc[nt][1] - mn0);
                sacc[nt][2] = fexp2(sacc[nt][2] - mn1);
                sacc[nt][3] = fexp2(sacc[nt][3] - mn1);
                rs0 += sacc[nt][0] + sacc[nt][1];
                rs1 += sacc[nt][2] + sacc[nt][3];
            }
            rs0 += __shfl_xor_sync(0xFFFFFFFFu, rs0, 1);
            rs0 += __shfl_xor_sync(0xFFFFFFFFu, rs0, 2);
            rs1 += __shfl_xor_sync(0xFFFFFFFFu, rs1, 1);
            rs1 += __shfl_xor_sync(0xFFFFFFFFu, rs1, 2);
            l0 = l0 * corr0 + rs0;
            l1 = l1 * corr1 + rs1;

#pragma unroll
            for (int nt = 0; nt < 8; nt++) {
                oacc[nt][0] *= corr0; oacc[nt][1] *= corr0;
                oacc[nt][2] *= corr1; oacc[nt][3] *= corr1;
            }

            // ---- O += P V : A-frag of P = pairwise-packed S C-frag (no shuffles)
#pragma unroll
            for (int ks = 0; ks < 4; ks++) {
                const uint32_t a0 = pack_h2(sacc[2*ks][0],   sacc[2*ks][1]);
                const uint32_t a1 = pack_h2(sacc[2*ks][2],   sacc[2*ks][3]);
                const uint32_t a2 = pack_h2(sacc[2*ks+1][0], sacc[2*ks+1][1]);
                const uint32_t a3 = pack_h2(sacc[2*ks+1][2], sacc[2*ks+1][3]);
#pragma unroll
                for (int p = 0; p < 4; p++) {
                    uint32_t vf[4];
                    LDMX4T(vf, vBase + (ks * 16 * kAStr + p * 16) * 2);
                    mma_f16(oacc[2*p][0], oacc[2*p][1], oacc[2*p][2], oacc[2*p][3],
                            a0, a1, a2, a3, vf[0], vf[1]);
                    mma_f16(oacc[2*p+1][0], oacc[2*p+1][1], oacc[2*p+1][2], oacc[2*p+1][3],
                            a0, a1, a2, a3, vf[2], vf[3]);
                }
            }
        }
        __syncthreads();
    }

    // ---- epilogue: ctx as fp16 (consumed by O-proj GEMM)
    const float inv0 = 1.f / l0;
    const float inv1 = 1.f / l1;
    __half* og = ctx + ((size_t)(b * kS + qb + wm + (lane >> 2))) * kDout + h * kHD;
    const int cbase = 2 * (lane & 3);
#pragma unroll
    for (int nt = 0; nt < 8; nt++) {
        const int col = nt * 8 + cbase;
        *(uint32_t*)&og[col] = pack_h2(oacc[nt][0] * inv0, oacc[nt][1] * inv0);
        *(uint32_t*)&og[(size_t)8 * kDout + col] =
            pack_h2(oacc[nt][2] * inv1, oacc[nt][3] * inv1);
    }
}

// ---------------------------------------------------------------------------
extern "C" void kernel_launch(void* const* d_in, const int* in_sizes, int n_in,
                              void* d_out, int out_size)
{
    const float* x  = (const float*)d_in[0];
    const float* Wq = (const float*)d_in[1];
    const float* Wk = (const float*)d_in[2];
    const float* Wv = (const float*)d_in[3];
    const float* Wo = (const float*)d_in[4];

    float* out    = (float*)d_out;
    float* keys   = out + (size_t)kM * kDout;
    float* values = keys + (size_t)kB * kNKV * kS * kHD;

    __half *Qh, *ctxh, *xH, *wqH, *wkH, *wvH, *woH, *kH, *vH;
    cudaGetSymbolAddress((void**)&Qh,   g_Qh);
    cudaGetSymbolAddress((void**)&ctxh, g_ctxh);
    cudaGetSymbolAddress((void**)&xH,   g_xH);
    cudaGetSymbolAddress((void**)&wqH,  g_wqH);
    cudaGetSymbolAddress((void**)&wkH,  g_wkH);
    cudaGetSymbolAddress((void**)&wvH,  g_wvH);
    cudaGetSymbolAddress((void**)&woH,  g_woH);
    cudaGetSymbolAddress((void**)&kH,   g_kH);
    cudaGetSymbolAddress((void**)&vH,   g_vH);

    cudaFuncSetAttribute(gemm_f16<0>, cudaFuncAttributeMaxDynamicSharedMemorySize, kGemmSmem);
    cudaFuncSetAttribute(gemm_f16<1>, cudaFuncAttributeMaxDynamicSharedMemorySize, kGemmSmem);
    cudaFuncSetAttribute(gemm_f16<2>, cudaFuncAttributeMaxDynamicSharedMemorySize, kGemmSmem);
    cudaFuncSetAttribute(attn_mma,    cudaFuncAttributeMaxDynamicSharedMemorySize, kAttSmem);

    // one-time fp32 -> fp16 conversion of x and weights
    cvt_f16<<<1024, 256>>>((const float4*)x,  (uint2*)xH,  kM * kDin / 4);
    cvt_f16<<<1024, 256>>>((const float4*)Wq, (uint2*)wqH, kDout * kDin / 4);
    cvt_f16<<<512,  256>>>((const float4*)Wk, (uint2*)wkH, kDkv * kDin / 4);
    cvt_f16<<<512,  256>>>((const float4*)Wv, (uint2*)wvH, kDkv * kDin / 4);
    cvt_f16<<<1024, 256>>>((const float4*)Wo, (uint2*)woH, kDin * kDout / 4);

    // Projections
    gemm_f16<2><<<dim3(kDout / BN, kM / BM), 256, kGemmSmem>>>(xH, wqH, nullptr, Qh, kM, kDout, kDin);
    gemm_f16<1><<<dim3(kDkv  / BN, kM / BM), 256, kGemmSmem>>>(xH, wkH, keys,   kH, kM, kDkv,  kDin);
    gemm_f16<1><<<dim3(kDkv  / BN, kM / BM), 256, kGemmSmem>>>(xH, wvH, values, vH, kM, kDkv,  kDin);

    // Causal GQA attention
    attn_mma<<<dim3(kS / 128, kB * kNH), 256, kAttSmem>>>(Qh, kH, vH, ctxh);

    // Output projection
    gemm_f16<0><<<dim3(kDout / BN, kM / BM), 256, kGemmSmem>>>(ctxh, woH, out, nullptr, kM, kDout, kDin);
}

// round 7
// speedup vs baseline: 9.0220x; 1.0878x over previous
#include <cuda_runtime.h>
#include <cuda_fp16.h>
#include <cstdint>
#include <cstddef>

// ---------------------------------------------------------------------------
// GroupedQueryAttention: B=2, S=2048, D_IN=2048, 32 heads x 64, 8 KV groups
// d_out: out [2,2048,2048] | keys [2,8,2048,64] | values [2,8,2048,64]
// fp16 mma.sync m16n8k16 (fp32 accum) everywhere.
// R7: single cvt pass, fused QKV GEMM, f16x2 exp + ones-mma row sums,
// reversed attention launch order.
// ---------------------------------------------------------------------------

namespace {
constexpr int kB    = 2;
constexpr int kS    = 2048;
constexpr int kDin  = 2048;
constexpr int kDout = 2048;
constexpr int kNH   = 32;
constexpr int kNKV  = 8;
constexpr int kHD   = 64;
constexpr int kM    = kB * kS;       // 4096
constexpr int kDkv  = kNKV * kHD;    // 512
constexpr int kNQKV = kDout + 2 * kDkv;   // 3072
constexpr float kQScale = 0.125f * 1.4426950408889634f;   // 1/sqrt(64)*log2(e)
constexpr uint32_t kOnesH2 = 0x3C003C00u;                 // half2(1,1)
}

// Scratch (device globals: no allocation allowed)
__device__ __half g_Qh  [(size_t)kM * kDout];      // pre-scaled fp16 Q
__device__ __half g_ctxh[(size_t)kM * kDout];      // fp16 ctx
__device__ __half g_xH  [(size_t)kM * kDin];
__device__ __half g_wH  [(size_t)kNQKV * kDin];    // [Wq;Wk;Wv] fp16
__device__ __half g_woH [(size_t)kDin * kDout];
__device__ __half g_kH  [(size_t)kB * kNKV * kS * kHD];
__device__ __half g_vH  [(size_t)kB * kNKV * kS * kHD];

// ------------------------- helpers -----------------------------------------
__device__ __forceinline__ uint32_t smem_u32(const void* p) {
    uint32_t a;
    asm("{ .reg .u64 t; cvta.to.shared.u64 t, %1; cvt.u32.u64 %0, t; }" : "=r"(a) : "l"(p));
    return a;
}
__device__ __forceinline__ uint32_t pack_h2(float lo, float hi) {
    uint32_t r;
    asm("cvt.rn.f16x2.f32 %0, %1, %2;" : "=r"(r) : "f"(hi), "f"(lo));
    return r;
}
__device__ __forceinline__ uint32_t h2exp2(uint32_t x) {
    uint32_t r;
    asm("ex2.approx.f16x2 %0, %1;" : "=r"(r) : "r"(x));
    return r;
}
__device__ __forceinline__ float fexp2(float x) {
    float r;
    asm("ex2.approx.f32 %0, %1;" : "=f"(r) : "f"(x));
    return r;
}
__device__ __forceinline__ void mma_f16(float& c0, float& c1, float& c2, float& c3,
                                        uint32_t a0, uint32_t a1, uint32_t a2, uint32_t a3,
                                        uint32_t b0, uint32_t b1) {
    asm volatile(
        "mma.sync.aligned.m16n8k16.row.col.f32.f16.f16.f32 "
        "{%0,%1,%2,%3}, {%4,%5,%6,%7}, {%8,%9}, {%0,%1,%2,%3};"
        : "+f"(c0), "+f"(c1), "+f"(c2), "+f"(c3)
        : "r"(a0), "r"(a1), "r"(a2), "r"(a3), "r"(b0), "r"(b1));
}
#define LDMX4(r, addr)                                                        \
    asm volatile("ldmatrix.sync.aligned.m8n8.x4.shared.b16 {%0,%1,%2,%3}, [%4];" \
        : "=r"((r)[0]), "=r"((r)[1]), "=r"((r)[2]), "=r"((r)[3]) : "r"(addr))
#define LDMX4T(r, addr)                                                       \
    asm volatile("ldmatrix.sync.aligned.m8n8.x4.trans.shared.b16 {%0,%1,%2,%3}, [%4];" \
        : "=r"((r)[0]), "=r"((r)[1]), "=r"((r)[2]), "=r"((r)[3]) : "r"(addr))
__device__ __forceinline__ void cp_async16(uint32_t dst, const void* src) {
    asm volatile("cp.async.cg.shared.global [%0], [%1], 16;" :: "r"(dst), "l"(src));
}
#define CP_COMMIT() asm volatile("cp.async.commit_group;" ::: "memory")
#define CP_WAIT(n)  asm volatile("cp.async.wait_group %0;" :: "n"(n) : "memory")

// ---------------------------------------------------------------------------
// Single-pass fp32 -> fp16 conversion of x, [Wq;Wk;Wv] and Wo
// ---------------------------------------------------------------------------
namespace {
constexpr int N4X = kM * kDin / 4;          // 2097152
constexpr int N4Q = kDout * kDin / 4;       // 1048576
constexpr int N4K = kDkv * kDin / 4;        // 262144
constexpr int N4O = kDin * kDout / 4;       // 1048576
constexpr int N4T = N4X + N4Q + 2 * N4K + N4O;
}

__global__ __launch_bounds__(256)
void cvt_all(const float4* __restrict__ x,  const float4* __restrict__ wq,
             const float4* __restrict__ wk, const float4* __restrict__ wv,
             const float4* __restrict__ wo)
{
    uint2* xH  = (uint2*)g_xH;
    uint2* wH  = (uint2*)g_wH;
    uint2* woH = (uint2*)g_woH;
    int i = blockIdx.x * blockDim.x + threadIdx.x;
    const int stride = gridDim.x * blockDim.x;
    for (; i < N4T; i += stride) {
        float4 v;
        uint2* dst;
        if (i < N4X)                       { v = x[i];                       dst = xH + i; }
        else if (i < N4X + N4Q)            { int j = i - N4X;                v = wq[j]; dst = wH + j; }
        else if (i < N4X + N4Q + N4K)      { int j = i - N4X - N4Q;          v = wk[j]; dst = wH + N4Q + j; }
        else if (i < N4X + N4Q + 2 * N4K)  { int j = i - N4X - N4Q - N4K;    v = wv[j]; dst = wH + N4Q + N4K + j; }
        else                               { int j = i - N4X - N4Q - 2*N4K;  v = wo[j]; dst = woH + j; }
        uint2 o;
        o.x = pack_h2(v.x, v.y);
        o.y = pack_h2(v.z, v.w);
        *dst = o;
    }
}

// ---------------------------------------------------------------------------
// GEMM core: BM=BN=128, BK=64, 256 threads, warp tile 32x64, 3-stage pipeline.
// Instantiated twice: fused-QKV epilogue and plain fp32 epilogue (O-proj).
// ---------------------------------------------------------------------------
namespace {
constexpr int BM = 128, BN = 128, BK = 64, STR = 72;      // STR in halfs
constexpr int kStageH   = (BM + BN) * STR;                // 18432 halfs
constexpr int kGemmSmem = 3 * kStageH * 2;                // 110592 B
}

// FUSED: 0 = plain fp32 C (O-proj), 1 = QKV fused epilogue
template <int FUSED>
__global__ __launch_bounds__(256, 2)
void gemm_f16(const __half* __restrict__ A, const __half* __restrict__ Bw,
              float* __restrict__ C, float* __restrict__ keys,
              float* __restrict__ values, int M, int N, int K)
{
    extern __shared__ __half smh[];
    const uint32_t smBase = smem_u32(smh);

    const int t    = threadIdx.x;
    const int lane = t & 31;
    const int wid  = t >> 5;
    const int wm   = (wid & 3) * 32;
    const int wn   = (wid >> 2) * 64;

    // grouped raster for L2 locality
    const int nbn = gridDim.x, nbm = gridDim.y;
    const int bid = blockIdx.y * nbn + blockIdx.x;
    const int ning = 8 * nbn;
    const int gid  = bid / ning;
    const int fm   = gid * 8;
    const int gsz  = min(8, nbm - fm);
    const int r    = bid % ning;
    const int rowBase = (fm + r % gsz) * BM;
    const int colBase = (r / gsz) * BN;

    float acc[2][8][4] = {};

    auto load_tile = [&](int kt, int st) {
        const __half* Ag = A  + (size_t)rowBase * K + kt * BK;
        const __half* Bg = Bw + (size_t)colBase * K + kt * BK;
        const uint32_t dst = smBase + st * kStageH * 2;
#pragma unroll
        for (int i = 0; i < 4; i++) {
            const int v = t + i * 256;
            const int rr = v >> 3, c8 = (v & 7) * 8;
            cp_async16(dst + (rr * STR + c8) * 2, Ag + (size_t)rr * K + c8);
        }
#pragma unroll
        for (int i = 0; i < 4; i++) {
            const int v = t + i * 256;
            const int rr = v >> 3, c8 = (v & 7) * 8;
            cp_async16(dst + (BM * STR + rr * STR + c8) * 2, Bg + (size_t)rr * K + c8);
        }
        CP_COMMIT();
    };

    const uint32_t aOff = ((wm + (lane & 15)) * STR + (lane >> 4) * 8) * 2;
    const uint32_t bOff = ((wn + ((lane >> 4) & 1) * 8 + (lane & 7)) * STR
                           + ((lane >> 3) & 1) * 8) * 2;

    const int NC = K / BK;
    load_tile(0, 0);
    load_tile(1, 1);

    int st = 0;
    for (int c = 0; c < NC; c++) {
        if (c + 1 < NC) { CP_WAIT(1); } else { CP_WAIT(0); }
        __syncthreads();
        if (c + 2 < NC) {
            int st2 = st + 2; if (st2 >= 3) st2 -= 3;
            load_tile(c + 2, st2);
        }

        const uint32_t ba = smBase + st * kStageH * 2;
        const uint32_t bb = ba + BM * STR * 2;
#pragma unroll
        for (int ks = 0; ks < 4; ks++) {
            uint32_t af[2][4];
            LDMX4(af[0], ba + aOff + (ks * 16) * 2);
            LDMX4(af[1], ba + aOff + (16 * STR + ks * 16) * 2);
#pragma unroll
            for (int p = 0; p < 4; p++) {
                uint32_t bf[4];
                LDMX4(bf, bb + bOff + (p * 16 * STR + ks * 16) * 2);
                mma_f16(acc[0][2*p][0], acc[0][2*p][1], acc[0][2*p][2], acc[0][2*p][3],
                        af[0][0], af[0][1], af[0][2], af[0][3], bf[0], bf[1]);
                mma_f16(acc[1][2*p][0], acc[1][2*p][1], acc[1][2*p][2], acc[1][2*p][3],
                        af[1][0], af[1][1], af[1][2], af[1][3], bf[0], bf[1]);
                mma_f16(acc[0][2*p+1][0], acc[0][2*p+1][1], acc[0][2*p+1][2], acc[0][2*p+1][3],
                        af[0][0], af[0][1], af[0][2], af[0][3], bf[2], bf[3]);
                mma_f16(acc[1][2*p+1][0], acc[1][2*p+1][1], acc[1][2*p+1][2], acc[1][2*p+1][3],
                        af[1][0], af[1][1], af[1][2], af[1][3], bf[2], bf[3]);
            }
        }
        if (++st == 3) st = 0;
    }

    // ---- epilogue
    if (FUSED == 0) {
#pragma unroll
        for (int mt = 0; mt < 2; mt++)
#pragma unroll
        for (int nt = 0; nt < 8; nt++) {
            const int row0 = rowBase + wm + mt * 16 + (lane >> 2);
            const int col  = colBase + wn + nt * 8 + 2 * (lane & 3);
            *(float2*)&C[(size_t)row0 * N + col] =
                make_float2(acc[mt][nt][0], acc[mt][nt][1]);
            *(float2*)&C[(size_t)(row0 + 8) * N + col] =
                make_float2(acc[mt][nt][2], acc[mt][nt][3]);
        }
    } else if (colBase < kDout) {
        // Q region: pre-scaled fp16 Q, row-major [kM, kDout]
#pragma unroll
        for (int mt = 0; mt < 2; mt++)
#pragma unroll
        for (int nt = 0; nt < 8; nt++) {
            const int row0 = rowBase + wm + mt * 16 + (lane >> 2);
            const int col  = colBase + wn + nt * 8 + 2 * (lane & 3);
            *(uint32_t*)&g_Qh[(size_t)row0 * kDout + col] =
                pack_h2(kQScale * acc[mt][nt][0], kQScale * acc[mt][nt][1]);
            *(uint32_t*)&g_Qh[(size_t)(row0 + 8) * kDout + col] =
                pack_h2(kQScale * acc[mt][nt][2], kQScale * acc[mt][nt][3]);
        }
    } else {
        // K or V region: KV-cache layout [b,g,s,d], fp32 + fp16 copies
        const bool isK = colBase < kDout + kDkv;
        float*  d32 = isK ? keys : values;
        __half* d16 = isK ? g_kH : g_vH;
        const int nBase = colBase - (isK ? kDout : (kDout + kDkv));
#pragma unroll
        for (int mt = 0; mt < 2; mt++)
#pragma unroll
        for (int nt = 0; nt < 8; nt++) {
            const int row0 = rowBase + wm + mt * 16 + (lane >> 2);
            const int nloc = nBase + wn + nt * 8 + 2 * (lane & 3);
            const int g = nloc >> 6, d = nloc & 63;
            {
                const int bb2 = row0 >> 11, ss = row0 & (kS - 1);
                const size_t o = ((((size_t)bb2 * kNKV + g) * kS + ss) << 6) + d;
                *(float2*)&d32[o] = make_float2(acc[mt][nt][0], acc[mt][nt][1]);
                *(uint32_t*)&d16[o] = pack_h2(acc[mt][nt][0], acc[mt][nt][1]);
            }
            {
                const int r1 = row0 + 8;
                const int bb2 = r1 >> 11, ss = r1 & (kS - 1);
                const size_t o = ((((size_t)bb2 * kNKV + g) * kS + ss) << 6) + d;
                *(float2*)&d32[o] = make_float2(acc[mt][nt][2], acc[mt][nt][3]);
                *(uint32_t*)&d16[o] = pack_h2(acc[mt][nt][2], acc[mt][nt][3]);
            }
        }
    }
}

// ---------------------------------------------------------------------------
// Causal GQA flash attention, fp16 mma (m16n8k16).
// 8 warps x 16 q-rows = 128 rows/block; 64-key tiles; grid = (S/128, B*NH),
// x reversed so heavy CTAs launch first.
// exp2-domain softmax computed directly in f16x2 (results ARE the packed
// PV A-fragments); row sums via ones-vector mma.
// ---------------------------------------------------------------------------
namespace {
constexpr int kAStr = 72;                                  // halfs
constexpr int kAttBufH = 2 * 64 * kAStr;                   // 9216 halfs/buffer
constexpr int kAttSmem = 2 * kAttBufH * 2;                 // 36864 B
}

__global__ __launch_bounds__(256, 2)
void attn_mma(const __half* __restrict__ Qh, const __half* __restrict__ KH,
              const __half* __restrict__ VH, __half* __restrict__ ctx)
{
    extern __shared__ __half smh[];
    const uint32_t smBase = smem_u32(smh);

    const int t    = threadIdx.x;
    const int lane = t & 31;
    const int wid  = t >> 5;
    const int bh = blockIdx.y;
    const int b  = bh >> 5;
    const int h  = bh & 31;
    const int g  = h >> 2;
    const int qx = (int)gridDim.x - 1 - (int)blockIdx.x;   // heavy blocks first
    const int qb = qx * 128;
    const int wm = wid * 16;

    // ---- stage Q -> smem -> ldmatrix A-fragments
    const __half* qg = Qh + ((size_t)(b * kS + qb)) * kDout + h * kHD;
#pragma unroll
    for (int i = 0; i < 4; i++) {
        const int v = t + i * 256;
        const int rr = v >> 3, c8 = (v & 7) * 8;
        *(uint4*)&smh[rr * kAStr + c8] = *(const uint4*)&qg[(size_t)rr * kDout + c8];
    }
    __syncthreads();
    uint32_t qf[4][4];
    {
        const uint32_t qOff = smBase + ((wm + (lane & 15)) * kAStr + (lane >> 4) * 8) * 2;
#pragma unroll
        for (int ks = 0; ks < 4; ks++) LDMX4(qf[ks], qOff + (ks * 16) * 2);
    }
    __syncthreads();

    float oacc[8][4] = {};
    float m0 = -1e30f, m1 = -1e30f, l0 = 0.f, l1 = 0.f;

    const __half* kg = KH + ((size_t)(b * kNKV + g)) * kS * kHD;
    const __half* vg = VH + ((size_t)(b * kNKV + g)) * kS * kHD;

    auto load_tile = [&](int kt, int buf) {
        const uint32_t dstK = smBase + buf * kAttBufH * 2;
        const uint32_t dstV = dstK + 64 * kAStr * 2;
#pragma unroll
        for (int i = 0; i < 2; i++) {
            const int v = t + i * 256;
            const int key = v >> 3, c8 = (v & 7) * 8;
            cp_async16(dstK + (key * kAStr + c8) * 2, kg + (size_t)(kt * 64 + key) * kHD + c8);
        }
#pragma unroll
        for (int i = 0; i < 2; i++) {
            const int v = t + i * 256;
            const int key = v >> 3, c8 = (v & 7) * 8;
            cp_async16(dstV + (key * kAStr + c8) * 2, vg + (size_t)(kt * 64 + key) * kHD + c8);
        }
        CP_COMMIT();
    };

    const uint32_t kOffRel =
        ((((lane >> 4) & 1) * 8 + (lane & 7)) * kAStr + ((lane >> 3) & 1) * 8) * 2;
    const uint32_t vOffRel =
        ((((lane >> 3) & 1) * 8 + (lane & 7)) * kAStr + ((lane >> 4) & 1) * 8) * 2;

    const int ntk = qx * 2 + 2;
    load_tile(0, 0);

    for (int kt = 0; kt < ntk; kt++) {
        const int buf = kt & 1;
        if (kt + 1 < ntk) { load_tile(kt + 1, buf ^ 1); CP_WAIT(1); }
        else              { CP_WAIT(0); }
        __syncthreads();

        if (kt * 64 <= qb + wm + 15) {              // warp-uniform skip
            const uint32_t kBase = smBase + buf * kAttBufH * 2 + kOffRel;
            const uint32_t vBase = smBase + buf * kAttBufH * 2 + 64 * kAStr * 2 + vOffRel;

            // ---- S = Q K^T
            float sacc[8][4] = {};
#pragma unroll
            for (int ks = 0; ks < 4; ks++) {
#pragma unroll
                for (int p = 0; p < 4; p++) {
                    uint32_t bf[4];
                    LDMX4(bf, kBase + (p * 16 * kAStr + ks * 16) * 2);
                    mma_f16(sacc[2*p][0], sacc[2*p][1], sacc[2*p][2], sacc[2*p][3],
                            qf[ks][0], qf[ks][1], qf[ks][2], qf[ks][3], bf[0], bf[1]);
                    mma_f16(sacc[2*p+1][0], sacc[2*p+1][1], sacc[2*p+1][2], sacc[2*p+1][3],
                            qf[ks][0], qf[ks][1], qf[ks][2], qf[ks][3], bf[2], bf[3]);
                }
            }

            // ---- causal mask
            const int r0 = qb + wm + (lane >> 2);
            const int r1 = r0 + 8;
            if (kt * 64 + 63 > qb + wm) {
#pragma unroll
                for (int nt = 0; nt < 8; nt++) {
                    const int c0 = kt * 64 + nt * 8 + 2 * (lane & 3);
                    if (c0     > r0) sacc[nt][0] = -1e30f;
                    if (c0 + 1 > r0) sacc[nt][1] = -1e30f;
                    if (c0     > r1) sacc[nt][2] = -1e30f;
                    if (c0 + 1 > r1) sacc[nt][3] = -1e30f;
                }
            }

            // ---- online softmax (base 2)
            float t0 = -1e30f, t1 = -1e30f;
#pragma unroll
            for (int nt = 0; nt < 8; nt++) {
                t0 = fmaxf(t0, fmaxf(sacc[nt][0], sacc[nt][1]));
                t1 = fmaxf(t1, fmaxf(sacc[nt][2], sacc[nt][3]));
            }
            t0 = fmaxf(t0, __shfl_xor_sync(0xFFFFFFFFu, t0, 1));
            t0 = fmaxf(t0, __shfl_xor_sync(0xFFFFFFFFu, t0, 2));
            t1 = fmaxf(t1, __shfl_xor_sync(0xFFFFFFFFu, t1, 1));
            t1 = fmaxf(t1, __shfl_xor_sync(0xFFFFFFFFu, t1, 2));
            const float mn0 = fmaxf(m0, t0);
            const float mn1 = fmaxf(m1, t1);
            const float corr0 = fexp2(m0 - mn0);
            const float corr1 = fexp2(m1 - mn1);
            m0 = mn0; m1 = mn1;

            // exp in f16x2: results are the packed PV A-fragment halves
            uint32_t p01[8], p23[8];
#pragma unroll
            for (int nt = 0; nt < 8; nt++) {
                p01[nt] = h2exp2(pack_h2(sacc[nt][0] - mn0, sacc[nt][1] - mn0));
                p23[nt] = h2exp2(pack_h2(sacc[nt][2] - mn1, sacc[nt][3] - mn1));
            }

#pragma unroll
            for (int nt = 0; nt < 8; nt++) {
                oacc[nt][0] *= corr0; oacc[nt][1] *= corr0;
                oacc[nt][2] *= corr1; oacc[nt][3] *= corr1;
            }

            // ---- O += P V  and row sums via ones-mma
            float lacc[4] = {};
#pragma unroll
            for (int ks = 0; ks < 4; ks++) {
                const uint32_t a0 = p01[2*ks];
                const uint32_t a1 = p23[2*ks];
                const uint32_t a2 = p01[2*ks+1];
                const uint32_t a3 = p23[2*ks+1];
                mma_f16(lacc[0], lacc[1], lacc[2], lacc[3],
                        a0, a1, a2, a3, kOnesH2, kOnesH2);
#pragma unroll
                for (int p = 0; p < 4; p++) {
                    uint32_t vf[4];
                    LDMX4T(vf, vBase + (ks * 16 * kAStr + p * 16) * 2);
                    mma_f16(oacc[2*p][0], oacc[2*p][1], oacc[2*p][2], oacc[2*p][3],
                            a0, a1, a2, a3, vf[0], vf[1]);
                    mma_f16(oacc[2*p+1][0], oacc[2*p+1][1], oacc[2*p+1][2], oacc[2*p+1][3],
                            a0, a1, a2, a3, vf[2], vf[3]);
                }
            }
            l0 = l0 * corr0 + lacc[0];
            l1 = l1 * corr1 + lacc[2];
        }
        __syncthreads();
    }

    // ---- epilogue: ctx as fp16 (consumed by O-proj GEMM)
    const float inv0 = 1.f / l0;
    const float inv1 = 1.f / l1;
    __half* og = ctx + ((size_t)(b * kS + qb + wm + (lane >> 2))) * kDout + h * kHD;
    const int cbase = 2 * (lane & 3);
#pragma unroll
    for (int nt = 0; nt < 8; nt++) {
        const int col = nt * 8 + cbase;
        *(uint32_t*)&og[col] = pack_h2(oacc[nt][0] * inv0, oacc[nt][1] * inv0);
        *(uint32_t*)&og[(size_t)8 * kDout + col] =
            pack_h2(oacc[nt][2] * inv1, oacc[nt][3] * inv1);
    }
}

// ---------------------------------------------------------------------------
extern "C" void kernel_launch(void* const* d_in, const int* in_sizes, int n_in,
                              void* d_out, int out_size)
{
    const float* x  = (const float*)d_in[0];
    const float* Wq = (const float*)d_in[1];
    const float* Wk = (const float*)d_in[2];
    const float* Wv = (const float*)d_in[3];
    const float* Wo = (const float*)d_in[4];

    float* out    = (float*)d_out;
    float* keys   = out + (size_t)kM * kDout;
    float* values = keys + (size_t)kB * kNKV * kS * kHD;

    __half *Qh, *ctxh, *xH, *wH, *woH, *kH, *vH;
    cudaGetSymbolAddress((void**)&Qh,   g_Qh);
    cudaGetSymbolAddress((void**)&ctxh, g_ctxh);
    cudaGetSymbolAddress((void**)&xH,   g_xH);
    cudaGetSymbolAddress((void**)&wH,   g_wH);
    cudaGetSymbolAddress((void**)&woH,  g_woH);
    cudaGetSymbolAddress((void**)&kH,   g_kH);
    cudaGetSymbolAddress((void**)&vH,   g_vH);

    cudaFuncSetAttribute(gemm_f16<0>, cudaFuncAttributeMaxDynamicSharedMemorySize, kGemmSmem);
    cudaFuncSetAttribute(gemm_f16<1>, cudaFuncAttributeMaxDynamicSharedMemorySize, kGemmSmem);
    cudaFuncSetAttribute(attn_mma,    cudaFuncAttributeMaxDynamicSharedMemorySize, kAttSmem);

    // single-pass fp32 -> fp16 conversion
    cvt_all<<<2048, 256>>>((const float4*)x, (const float4*)Wq, (const float4*)Wk,
                           (const float4*)Wv, (const float4*)Wo);

    // fused Q/K/V projection (N = 3072)
    gemm_f16<1><<<dim3(kNQKV / BN, kM / BM), 256, kGemmSmem>>>(
        xH, wH, nullptr, keys, values, kM, kNQKV, kDin);

    // causal GQA attention
    attn_mma<<<dim3(kS / 128, kB * kNH), 256, kAttSmem>>>(Qh, kH, vH, ctxh);

    // output projection
    gemm_f16<0><<<dim3(kDout / BN, kM / BM), 256, kGemmSmem>>>(
        ctxh, woH, out, nullptr, nullptr, kM, kDout, kDin);
}